// round 2
// baseline (speedup 1.0000x reference)
#include <cuda_runtime.h>
#include <math.h>

// ---------------- problem constants ----------------
#define D_MODEL 1024
#define NH      16
#define DK_     64
#define DFF_    4096
#define B_      4
#define LT_     1024
#define LS_     1024
#define NTOK    (B_ * LT_)   // 4096 rows

// ---------------- scratch (static device globals; no allocs allowed) -------
__device__ float g_ln [NTOK * D_MODEL];
__device__ float g_q  [NTOK * D_MODEL];
__device__ float g_k  [NTOK * D_MODEL];
__device__ float g_v  [NTOK * D_MODEL];
__device__ float g_ctx[NTOK * D_MODEL];
__device__ float g_x1 [NTOK * D_MODEL];
__device__ float g_x2 [NTOK * D_MODEL];
__device__ float g_ffn[NTOK * DFF_];

// ---------------- LayerNorm: one block per row, 256 threads ----------------
__global__ void ln_kernel(const float* __restrict__ x, const float* __restrict__ g,
                          const float* __restrict__ b, float* __restrict__ y) {
    int row = blockIdx.x;
    const float* xr = x + (size_t)row * D_MODEL;
    float*       yr = y + (size_t)row * D_MODEL;
    int t = threadIdx.x;                 // 0..255, each owns one float4

    float4 v = *(const float4*)&xr[t * 4];
    float s  = v.x + v.y + v.z + v.w;
    float ss = v.x * v.x + v.y * v.y + v.z * v.z + v.w * v.w;

    #pragma unroll
    for (int o = 16; o; o >>= 1) {
        s  += __shfl_xor_sync(0xffffffffu, s,  o);
        ss += __shfl_xor_sync(0xffffffffu, ss, o);
    }
    __shared__ float rs[8], rss[8];
    int w = t >> 5, lane = t & 31;
    if (lane == 0) { rs[w] = s; rss[w] = ss; }
    __syncthreads();
    float tot = 0.f, tot2 = 0.f;
    #pragma unroll
    for (int i = 0; i < 8; i++) { tot += rs[i]; tot2 += rss[i]; }

    float mu  = tot * (1.0f / D_MODEL);
    float var = tot2 * (1.0f / D_MODEL) - mu * mu;
    float r   = rsqrtf(var + 1e-5f);

    float4 gv = *(const float4*)&g[t * 4];
    float4 bv = *(const float4*)&b[t * 4];
    float4 o;
    o.x = (v.x - mu) * r * gv.x + bv.x;
    o.y = (v.y - mu) * r * gv.y + bv.y;
    o.z = (v.z - mu) * r * gv.z + bv.z;
    o.w = (v.w - mu) * r * gv.w + bv.w;
    *(float4*)&yr[t * 4] = o;
}

// ---------------- GELU (tanh approximation, matches jax.nn.gelu default) ---
__device__ __forceinline__ float gelu_f(float x) {
    float x3 = x * x * x;
    float t  = tanhf(0.7978845608028654f * (x + 0.044715f * x3));
    return 0.5f * x * (1.0f + t);
}

// ---------------- SGEMM: C[M,N] = A[M,K] @ W[K,N] + bias (+res) (gelu) -----
// BM=BN=128, BK=8, 256 threads, 8x8 micro-tile per thread.
#define BM 128
#define BN 128
#define BK 8

__global__ __launch_bounds__(256, 2)
void sgemm_kernel(const float* __restrict__ A, const float* __restrict__ W,
                  const float* __restrict__ bias, const float* __restrict__ residual,
                  float* __restrict__ C, int M, int N, int K, int do_gelu) {
    __shared__ float As[BK][BM];
    __shared__ float Bs[BK][BN];

    int tid  = threadIdx.x;
    int tx   = tid & 15;          // 0..15  -> 8 cols each
    int ty   = tid >> 4;          // 0..15  -> 8 rows each
    int row0 = blockIdx.y * BM;
    int col0 = blockIdx.x * BN;

    // A tile loader: 128x8 floats, one float4 per thread
    int a_r = tid >> 1;           // 0..127
    int a_c = (tid & 1) * 4;      // 0 or 4
    // B tile loader: 8x128 floats, one float4 per thread
    int b_r = tid >> 5;           // 0..7
    int b_c = (tid & 31) * 4;     // 0..124

    float acc[8][8] = {};

    for (int k0 = 0; k0 < K; k0 += BK) {
        float4 av = *(const float4*)&A[(size_t)(row0 + a_r) * K + k0 + a_c];
        As[a_c + 0][a_r] = av.x;
        As[a_c + 1][a_r] = av.y;
        As[a_c + 2][a_r] = av.z;
        As[a_c + 3][a_r] = av.w;
        *(float4*)&Bs[b_r][b_c] = *(const float4*)&W[(size_t)(k0 + b_r) * N + col0 + b_c];
        __syncthreads();

        #pragma unroll
        for (int kk = 0; kk < BK; kk++) {
            float af[8], bf[8];
            *(float4*)&af[0] = *(const float4*)&As[kk][ty * 8];
            *(float4*)&af[4] = *(const float4*)&As[kk][ty * 8 + 4];
            *(float4*)&bf[0] = *(const float4*)&Bs[kk][tx * 8];
            *(float4*)&bf[4] = *(const float4*)&Bs[kk][tx * 8 + 4];
            #pragma unroll
            for (int i = 0; i < 8; i++)
                #pragma unroll
                for (int j = 0; j < 8; j++)
                    acc[i][j] = fmaf(af[i], bf[j], acc[i][j]);
        }
        __syncthreads();
    }

    // epilogue: bias + optional residual + optional gelu, float4 stores
    #pragma unroll
    for (int i = 0; i < 8; i++) {
        size_t r = (size_t)(row0 + ty * 8 + i);
        #pragma unroll
        for (int j = 0; j < 8; j += 4) {
            int c0 = col0 + tx * 8 + j;
            float4 bv = *(const float4*)&bias[c0];
            float4 o;
            o.x = acc[i][j + 0] + bv.x;
            o.y = acc[i][j + 1] + bv.y;
            o.z = acc[i][j + 2] + bv.z;
            o.w = acc[i][j + 3] + bv.w;
            if (residual) {
                float4 rv = *(const float4*)&residual[r * N + c0];
                o.x += rv.x; o.y += rv.y; o.z += rv.z; o.w += rv.w;
            }
            if (do_gelu) {
                o.x = gelu_f(o.x); o.y = gelu_f(o.y);
                o.z = gelu_f(o.z); o.w = gelu_f(o.w);
            }
            *(float4*)&C[r * N + c0] = o;
        }
    }
}

// ---------------- attention: one warp per query row, online softmax --------
// Q,K,V laid out [B, L, H*DK] (head h at columns h*64). 8 warps/block.
__global__ void attn_kernel(const float* __restrict__ Q, const float* __restrict__ K,
                            const float* __restrict__ V,
                            const unsigned char* __restrict__ mask,
                            float* __restrict__ O, int Lq, int Lk, int causal) {
    int tile = blockIdx.x;
    int qt   = tile % (Lq / 8);
    int bh   = tile / (Lq / 8);
    int h    = bh % NH;
    int b    = bh / NH;
    int w    = threadIdx.x >> 5;
    int lane = threadIdx.x & 31;
    int q    = qt * 8 + w;

    const float* qp = Q + ((size_t)(b * Lq + q)) * D_MODEL + h * DK_;
    float2 qv = *(const float2*)&qp[lane * 2];
    qv.x *= 0.125f;  // 1/sqrt(64)
    qv.y *= 0.125f;

    const float* kb = K + ((size_t)b * Lk) * D_MODEL + h * DK_;
    const float* vb = V + ((size_t)b * Lk) * D_MODEL + h * DK_;
    const unsigned char* mrow = mask ? mask + ((size_t)(b * Lq + q)) * Lk : nullptr;

    float m = -3.0e38f, l = 0.f, a0 = 0.f, a1 = 0.f;
    int kend = causal ? (q + 1) : Lk;

    for (int kk = 0; kk < kend; kk++) {
        if (mrow && mrow[kk]) continue;   // masked -> weight 0
        float2 kv = *(const float2*)&kb[(size_t)kk * D_MODEL + lane * 2];
        float s = qv.x * kv.x + qv.y * kv.y;
        #pragma unroll
        for (int o = 16; o; o >>= 1) s += __shfl_xor_sync(0xffffffffu, s, o);

        float mn   = fmaxf(m, s);
        float corr = __expf(m - mn);
        float p    = __expf(s - mn);
        float2 vv  = *(const float2*)&vb[(size_t)kk * D_MODEL + lane * 2];
        l  = l  * corr + p;
        a0 = a0 * corr + p * vv.x;
        a1 = a1 * corr + p * vv.y;
        m  = mn;
    }

    float inv = 1.0f / l;
    float* op = O + ((size_t)(b * Lq + q)) * D_MODEL + h * DK_;
    float2 o2; o2.x = a0 * inv; o2.y = a1 * inv;
    *(float2*)&op[lane * 2] = o2;
}

// ---------------- launch ---------------------------------------------------
extern "C" void kernel_launch(void* const* d_in, const int* in_sizes, int n_in,
                              void* d_out, int out_size) {
    const float* tgt      = (const float*)d_in[0];
    const float* memory   = (const float*)d_in[1];
    const unsigned char* src_pad = (const unsigned char*)d_in[2];
    // d_in[3] = tgt_mask (causal triu) — handled via causal flag
    const float* self_wq  = (const float*)d_in[4];
    const float* self_bq  = (const float*)d_in[5];
    const float* self_wk  = (const float*)d_in[6];
    const float* self_bk  = (const float*)d_in[7];
    const float* self_wv  = (const float*)d_in[8];
    const float* self_bv  = (const float*)d_in[9];
    const float* self_wo  = (const float*)d_in[10];
    const float* self_bo  = (const float*)d_in[11];
    const float* cross_wq = (const float*)d_in[12];
    const float* cross_bq = (const float*)d_in[13];
    const float* cross_wk = (const float*)d_in[14];
    const float* cross_bk = (const float*)d_in[15];
    const float* cross_wv = (const float*)d_in[16];
    const float* cross_bv = (const float*)d_in[17];
    const float* cross_wo = (const float*)d_in[18];
    const float* cross_bo = (const float*)d_in[19];
    const float* ln1_g    = (const float*)d_in[20];
    const float* ln1_b    = (const float*)d_in[21];
    const float* ln2_g    = (const float*)d_in[22];
    const float* ln2_b    = (const float*)d_in[23];
    const float* ln3_g    = (const float*)d_in[24];
    const float* ln3_b    = (const float*)d_in[25];
    const float* ffn_w1   = (const float*)d_in[26];
    const float* ffn_b1   = (const float*)d_in[27];
    const float* ffn_w2   = (const float*)d_in[28];
    const float* ffn_b2   = (const float*)d_in[29];

    float *ln, *q, *k, *v, *ctx, *x1, *x2, *ffn;
    cudaGetSymbolAddress((void**)&ln,  g_ln);
    cudaGetSymbolAddress((void**)&q,   g_q);
    cudaGetSymbolAddress((void**)&k,   g_k);
    cudaGetSymbolAddress((void**)&v,   g_v);
    cudaGetSymbolAddress((void**)&ctx, g_ctx);
    cudaGetSymbolAddress((void**)&x1,  g_x1);
    cudaGetSymbolAddress((void**)&x2,  g_x2);
    cudaGetSymbolAddress((void**)&ffn, g_ffn);

    float* out = (float*)d_out;

    dim3 gD(D_MODEL / BN, NTOK / BM);   // (8, 32)  for N=1024
    dim3 gF(DFF_ / BN,   NTOK / BM);    // (32, 32) for N=4096
    int attn_grid = B_ * NH * (LT_ / 8);

    // ---- sublayer 1: self-attention (pre-norm) ----
    ln_kernel<<<NTOK, 256>>>(tgt, ln1_g, ln1_b, ln);
    sgemm_kernel<<<gD, 256>>>(ln, self_wq, self_bq, nullptr, q,  NTOK, D_MODEL, D_MODEL, 0);
    sgemm_kernel<<<gD, 256>>>(ln, self_wk, self_bk, nullptr, k,  NTOK, D_MODEL, D_MODEL, 0);
    sgemm_kernel<<<gD, 256>>>(ln, self_wv, self_bv, nullptr, v,  NTOK, D_MODEL, D_MODEL, 0);
    attn_kernel<<<attn_grid, 256>>>(q, k, v, nullptr, ctx, LT_, LT_, 1);
    sgemm_kernel<<<gD, 256>>>(ctx, self_wo, self_bo, tgt, x1, NTOK, D_MODEL, D_MODEL, 0);

    // ---- sublayer 2: cross-attention (pre-norm; K/V from raw memory) ----
    ln_kernel<<<NTOK, 256>>>(x1, ln2_g, ln2_b, ln);
    sgemm_kernel<<<gD, 256>>>(ln,     cross_wq, cross_bq, nullptr, q, NTOK, D_MODEL, D_MODEL, 0);
    sgemm_kernel<<<gD, 256>>>(memory, cross_wk, cross_bk, nullptr, k, NTOK, D_MODEL, D_MODEL, 0);
    sgemm_kernel<<<gD, 256>>>(memory, cross_wv, cross_bv, nullptr, v, NTOK, D_MODEL, D_MODEL, 0);
    attn_kernel<<<attn_grid, 256>>>(q, k, v, src_pad, ctx, LT_, LS_, 0);
    sgemm_kernel<<<gD, 256>>>(ctx, cross_wo, cross_bo, x1, x2, NTOK, D_MODEL, D_MODEL, 0);

    // ---- sublayer 3: FFN (pre-norm) ----
    ln_kernel<<<NTOK, 256>>>(x2, ln3_g, ln3_b, ln);
    sgemm_kernel<<<gF, 256>>>(ln,  ffn_w1, ffn_b1, nullptr, ffn, NTOK, DFF_,    D_MODEL, 1);
    sgemm_kernel<<<gD, 256>>>(ffn, ffn_w2, ffn_b2, x2, out,      NTOK, D_MODEL, DFF_,    0);
}

// round 3
// speedup vs baseline: 2.5841x; 2.5841x over previous
#include <cuda_runtime.h>
#include <math.h>

// ---------------- problem constants ----------------
#define D_MODEL 1024
#define NH      16
#define DK_     64
#define DFF_    4096
#define B_      4
#define LT_     1024
#define LS_     1024
#define NTOK    (B_ * LT_)   // 4096 rows

// ---------------- scratch (static device globals; no allocs allowed) -------
__device__ float g_ln [NTOK * D_MODEL];
__device__ float g_q  [NTOK * D_MODEL];
__device__ float g_k  [NTOK * D_MODEL];
__device__ float g_v  [NTOK * D_MODEL];
__device__ float g_ctx[NTOK * D_MODEL];
__device__ float g_x1 [NTOK * D_MODEL];
__device__ float g_x2 [NTOK * D_MODEL];
__device__ float g_ffn[NTOK * DFF_];

// ---------------- LayerNorm: one block per row, 256 threads ----------------
__global__ void ln_kernel(const float* __restrict__ x, const float* __restrict__ g,
                          const float* __restrict__ b, float* __restrict__ y) {
    int row = blockIdx.x;
    const float* xr = x + (size_t)row * D_MODEL;
    float*       yr = y + (size_t)row * D_MODEL;
    int t = threadIdx.x;

    float4 v = *(const float4*)&xr[t * 4];
    float s  = v.x + v.y + v.z + v.w;
    float ss = v.x * v.x + v.y * v.y + v.z * v.z + v.w * v.w;

    #pragma unroll
    for (int o = 16; o; o >>= 1) {
        s  += __shfl_xor_sync(0xffffffffu, s,  o);
        ss += __shfl_xor_sync(0xffffffffu, ss, o);
    }
    __shared__ float rs[8], rss[8];
    int w = t >> 5, lane = t & 31;
    if (lane == 0) { rs[w] = s; rss[w] = ss; }
    __syncthreads();
    float tot = 0.f, tot2 = 0.f;
    #pragma unroll
    for (int i = 0; i < 8; i++) { tot += rs[i]; tot2 += rss[i]; }

    float mu  = tot * (1.0f / D_MODEL);
    float var = tot2 * (1.0f / D_MODEL) - mu * mu;
    float r   = rsqrtf(var + 1e-5f);

    float4 gv = *(const float4*)&g[t * 4];
    float4 bv = *(const float4*)&b[t * 4];
    float4 o;
    o.x = (v.x - mu) * r * gv.x + bv.x;
    o.y = (v.y - mu) * r * gv.y + bv.y;
    o.z = (v.z - mu) * r * gv.z + bv.z;
    o.w = (v.w - mu) * r * gv.w + bv.w;
    *(float4*)&yr[t * 4] = o;
}

// ---------------- GELU (tanh approximation, matches jax.nn.gelu default) ---
__device__ __forceinline__ float gelu_f(float x) {
    float x3 = x * x * x;
    float t  = tanhf(0.7978845608028654f * (x + 0.044715f * x3));
    return 0.5f * x * (1.0f + t);
}

// ---------------- SGEMM: C[M,N] = A[M,K] @ W[K,N] + bias (+res) (gelu) -----
// BM=BN=128, BK=16, 256 threads, 8x8 micro-tile per thread.
#define BM 128
#define BN 128
#define BK 16

__global__ __launch_bounds__(256, 2)
void sgemm_kernel(const float* __restrict__ A, const float* __restrict__ W,
                  const float* __restrict__ bias, const float* __restrict__ residual,
                  float* __restrict__ C, int M, int N, int K, int do_gelu) {
    __shared__ float As[BK][BM];
    __shared__ float Bs[BK][BN];

    int tid  = threadIdx.x;
    int tx   = tid & 15;
    int ty   = tid >> 4;
    int row0 = blockIdx.y * BM;
    int col0 = blockIdx.x * BN;

    // A loader: 128 rows x 16 cols; each thread: row=tid>>1, 8 cols at (tid&1)*8
    int a_r = tid >> 1;
    int a_c = (tid & 1) * 8;
    // B loader: 16 rows x 128 cols; each thread: row=tid>>4, 8 cols at (tid&15)*8
    int b_r = tid >> 4;
    int b_c = (tid & 15) * 8;

    float acc[8][8] = {};

    for (int k0 = 0; k0 < K; k0 += BK) {
        #pragma unroll
        for (int q = 0; q < 2; q++) {
            float4 av = *(const float4*)&A[(size_t)(row0 + a_r) * K + k0 + a_c + q * 4];
            As[a_c + q * 4 + 0][a_r] = av.x;
            As[a_c + q * 4 + 1][a_r] = av.y;
            As[a_c + q * 4 + 2][a_r] = av.z;
            As[a_c + q * 4 + 3][a_r] = av.w;
            *(float4*)&Bs[b_r][b_c + q * 4] =
                *(const float4*)&W[(size_t)(k0 + b_r) * N + col0 + b_c + q * 4];
        }
        __syncthreads();

        #pragma unroll
        for (int kk = 0; kk < BK; kk++) {
            float af[8], bf[8];
            *(float4*)&af[0] = *(const float4*)&As[kk][ty * 8];
            *(float4*)&af[4] = *(const float4*)&As[kk][ty * 8 + 4];
            *(float4*)&bf[0] = *(const float4*)&Bs[kk][tx * 8];
            *(float4*)&bf[4] = *(const float4*)&Bs[kk][tx * 8 + 4];
            #pragma unroll
            for (int i = 0; i < 8; i++)
                #pragma unroll
                for (int j = 0; j < 8; j++)
                    acc[i][j] = fmaf(af[i], bf[j], acc[i][j]);
        }
        __syncthreads();
    }

    #pragma unroll
    for (int i = 0; i < 8; i++) {
        size_t r = (size_t)(row0 + ty * 8 + i);
        #pragma unroll
        for (int j = 0; j < 8; j += 4) {
            int c0 = col0 + tx * 8 + j;
            float4 bv = *(const float4*)&bias[c0];
            float4 o;
            o.x = acc[i][j + 0] + bv.x;
            o.y = acc[i][j + 1] + bv.y;
            o.z = acc[i][j + 2] + bv.z;
            o.w = acc[i][j + 3] + bv.w;
            if (residual) {
                float4 rv = *(const float4*)&residual[r * N + c0];
                o.x += rv.x; o.y += rv.y; o.z += rv.z; o.w += rv.w;
            }
            if (do_gelu) {
                o.x = gelu_f(o.x); o.y = gelu_f(o.y);
                o.z = gelu_f(o.z); o.w = gelu_f(o.w);
            }
            *(float4*)&C[r * N + c0] = o;
        }
    }
}

// ---------------- tiled flash attention ------------------------------------
// Block: one (b, h, 64-query tile). 256 threads = 8 warps, warp w owns q rows
// [w*8, w*8+8). Lane l owns key cols {l, l+32} (scores) / d cols {l, l+32} (PV).
// Dynamic smem: Qs[64][64] | KsT[64][65] (reused as Ps[64][64]) | Vs[64][64]
#define AT 64
#define KST_STRIDE 65
#define SMEM_ATTN ((4096 + 64 * KST_STRIDE + 4096) * 4)

__global__ __launch_bounds__(256)
void attn_tile_kernel(const float* __restrict__ Q, const float* __restrict__ K,
                      const float* __restrict__ V,
                      const unsigned char* __restrict__ mask,
                      float* __restrict__ O, int Lq, int Lk, int causal) {
    extern __shared__ float sm[];
    float* Qs  = sm;                       // [64][64]
    float* KsT = sm + 4096;                // [64][65], transposed: [d][key]
    float* Ps  = sm + 4096;                // [64][64] overlay (after scores)
    float* Vs  = sm + 4096 + 64 * KST_STRIDE; // [64][64]  [key][d]

    int qt = blockIdx.x;
    int h  = blockIdx.y;
    int b  = blockIdx.z;
    int tid = threadIdx.x, w = tid >> 5, l = tid & 31;
    int q0 = qt * AT;

    const float* Qb = Q + ((size_t)(b * Lq + q0)) * D_MODEL + h * DK_;
    const float* Kb = K + ((size_t)b * Lk) * D_MODEL + h * DK_;
    const float* Vb = V + ((size_t)b * Lk) * D_MODEL + h * DK_;

    // load Q tile (scaled by 1/sqrt(64))
    #pragma unroll
    for (int p = 0; p < 4; p++) {
        int idx = p * 256 + tid;          // 0..1023 over 64 rows x 16 float4
        int r = idx >> 4, c4 = (idx & 15) * 4;
        float4 v4 = *(const float4*)&Qb[(size_t)r * D_MODEL + c4];
        v4.x *= 0.125f; v4.y *= 0.125f; v4.z *= 0.125f; v4.w *= 0.125f;
        *(float4*)&Qs[r * 64 + c4] = v4;
    }

    float m_i[8], l_i[8], o0[8], o1[8];
    #pragma unroll
    for (int i = 0; i < 8; i++) { m_i[i] = -3.0e38f; l_i[i] = 0.f; o0[i] = 0.f; o1[i] = 0.f; }

    int ntile = causal ? (qt + 1) : (Lk / AT);

    for (int kt = 0; kt < ntile; kt++) {
        int kg = kt * AT;
        __syncthreads();   // previous iteration done with Vs / Ps

        // load K (transposed) and V tiles
        #pragma unroll
        for (int p = 0; p < 4; p++) {
            int idx = p * 256 + tid;
            int r = idx >> 4, c4 = (idx & 15) * 4;   // r = key, c4 = d
            float4 kv = *(const float4*)&Kb[(size_t)(kg + r) * D_MODEL + c4];
            KsT[(c4 + 0) * KST_STRIDE + r] = kv.x;
            KsT[(c4 + 1) * KST_STRIDE + r] = kv.y;
            KsT[(c4 + 2) * KST_STRIDE + r] = kv.z;
            KsT[(c4 + 3) * KST_STRIDE + r] = kv.w;
            float4 vv = *(const float4*)&Vb[(size_t)(kg + r) * D_MODEL + c4];
            *(float4*)&Vs[r * 64 + c4] = vv;
        }
        __syncthreads();

        // ---- scores: s[i][{l, l+32}] = q_row_i . k_col ----
        float s0[8] = {}, s1[8] = {};
        #pragma unroll
        for (int d0 = 0; d0 < 64; d0 += 4) {
            float ka[4], kb2[4];
            #pragma unroll
            for (int j = 0; j < 4; j++) {
                ka[j]  = KsT[(d0 + j) * KST_STRIDE + l];
                kb2[j] = KsT[(d0 + j) * KST_STRIDE + l + 32];
            }
            #pragma unroll
            for (int i = 0; i < 8; i++) {
                float4 qv = *(const float4*)&Qs[(w * 8 + i) * 64 + d0];
                s0[i] = fmaf(qv.x, ka[0],  s0[i]);
                s0[i] = fmaf(qv.y, ka[1],  s0[i]);
                s0[i] = fmaf(qv.z, ka[2],  s0[i]);
                s0[i] = fmaf(qv.w, ka[3],  s0[i]);
                s1[i] = fmaf(qv.x, kb2[0], s1[i]);
                s1[i] = fmaf(qv.y, kb2[1], s1[i]);
                s1[i] = fmaf(qv.z, kb2[2], s1[i]);
                s1[i] = fmaf(qv.w, kb2[3], s1[i]);
            }
        }

        // ---- masking ----
        if (mask) {
            const unsigned char* mb = mask + ((size_t)(b * Lq + q0 + w * 8)) * Lk + kg;
            #pragma unroll
            for (int i = 0; i < 8; i++) {
                if (mb[(size_t)i * Lk + l])      s0[i] = -3.0e38f;
                if (mb[(size_t)i * Lk + l + 32]) s1[i] = -3.0e38f;
            }
        }
        if (causal && kt == qt) {
            #pragma unroll
            for (int i = 0; i < 8; i++) {
                int row = w * 8 + i;               // local; kg == q0 here
                if (l > row)      s0[i] = -3.0e38f;
                if (l + 32 > row) s1[i] = -3.0e38f;
            }
        }

        __syncthreads();   // all warps done reading KsT (Ps overlays it)

        // ---- online softmax + write P ----
        #pragma unroll
        for (int i = 0; i < 8; i++) {
            float smax = fmaxf(s0[i], s1[i]);
            #pragma unroll
            for (int o = 16; o; o >>= 1) smax = fmaxf(smax, __shfl_xor_sync(0xffffffffu, smax, o));
            float mn   = fmaxf(m_i[i], smax);
            float corr = __expf(m_i[i] - mn);
            float p0   = __expf(s0[i] - mn);
            float p1   = __expf(s1[i] - mn);
            float ps   = p0 + p1;
            #pragma unroll
            for (int o = 16; o; o >>= 1) ps += __shfl_xor_sync(0xffffffffu, ps, o);
            l_i[i] = l_i[i] * corr + ps;
            m_i[i] = mn;
            o0[i] *= corr; o1[i] *= corr;
            Ps[(w * 8 + i) * 64 + l]      = p0;
            Ps[(w * 8 + i) * 64 + l + 32] = p1;
        }
        __syncwarp();

        // ---- PV: o[i][{l, l+32}] += sum_k P[i][k] * V[k][{l, l+32}] ----
        #pragma unroll
        for (int k0 = 0; k0 < 64; k0 += 4) {
            float v0[4], v1[4];
            #pragma unroll
            for (int j = 0; j < 4; j++) {
                v0[j] = Vs[(k0 + j) * 64 + l];
                v1[j] = Vs[(k0 + j) * 64 + l + 32];
            }
            #pragma unroll
            for (int i = 0; i < 8; i++) {
                float4 p4 = *(const float4*)&Ps[(w * 8 + i) * 64 + k0];
                o0[i] = fmaf(p4.x, v0[0], o0[i]);
                o0[i] = fmaf(p4.y, v0[1], o0[i]);
                o0[i] = fmaf(p4.z, v0[2], o0[i]);
                o0[i] = fmaf(p4.w, v0[3], o0[i]);
                o1[i] = fmaf(p4.x, v1[0], o1[i]);
                o1[i] = fmaf(p4.y, v1[1], o1[i]);
                o1[i] = fmaf(p4.z, v1[2], o1[i]);
                o1[i] = fmaf(p4.w, v1[3], o1[i]);
            }
        }
    }

    // ---- epilogue ----
    #pragma unroll
    for (int i = 0; i < 8; i++) {
        float inv = 1.0f / l_i[i];
        float* op = O + ((size_t)(b * Lq + q0 + w * 8 + i)) * D_MODEL + h * DK_;
        op[l]      = o0[i] * inv;
        op[l + 32] = o1[i] * inv;
    }
}

// ---------------- launch ---------------------------------------------------
extern "C" void kernel_launch(void* const* d_in, const int* in_sizes, int n_in,
                              void* d_out, int out_size) {
    const float* tgt      = (const float*)d_in[0];
    const float* memory   = (const float*)d_in[1];
    const unsigned char* src_pad = (const unsigned char*)d_in[2];
    // d_in[3] = tgt_mask (causal triu) — handled via causal flag
    const float* self_wq  = (const float*)d_in[4];
    const float* self_bq  = (const float*)d_in[5];
    const float* self_wk  = (const float*)d_in[6];
    const float* self_bk  = (const float*)d_in[7];
    const float* self_wv  = (const float*)d_in[8];
    const float* self_bv  = (const float*)d_in[9];
    const float* self_wo  = (const float*)d_in[10];
    const float* self_bo  = (const float*)d_in[11];
    const float* cross_wq = (const float*)d_in[12];
    const float* cross_bq = (const float*)d_in[13];
    const float* cross_wk = (const float*)d_in[14];
    const float* cross_bk = (const float*)d_in[15];
    const float* cross_wv = (const float*)d_in[16];
    const float* cross_bv = (const float*)d_in[17];
    const float* cross_wo = (const float*)d_in[18];
    const float* cross_bo = (const float*)d_in[19];
    const float* ln1_g    = (const float*)d_in[20];
    const float* ln1_b    = (const float*)d_in[21];
    const float* ln2_g    = (const float*)d_in[22];
    const float* ln2_b    = (const float*)d_in[23];
    const float* ln3_g    = (const float*)d_in[24];
    const float* ln3_b    = (const float*)d_in[25];
    const float* ffn_w1   = (const float*)d_in[26];
    const float* ffn_b1   = (const float*)d_in[27];
    const float* ffn_w2   = (const float*)d_in[28];
    const float* ffn_b2   = (const float*)d_in[29];

    float *ln, *q, *k, *v, *ctx, *x1, *x2, *ffn;
    cudaGetSymbolAddress((void**)&ln,  g_ln);
    cudaGetSymbolAddress((void**)&q,   g_q);
    cudaGetSymbolAddress((void**)&k,   g_k);
    cudaGetSymbolAddress((void**)&v,   g_v);
    cudaGetSymbolAddress((void**)&ctx, g_ctx);
    cudaGetSymbolAddress((void**)&x1,  g_x1);
    cudaGetSymbolAddress((void**)&x2,  g_x2);
    cudaGetSymbolAddress((void**)&ffn, g_ffn);

    float* out = (float*)d_out;

    cudaFuncSetAttribute(attn_tile_kernel,
                         cudaFuncAttributeMaxDynamicSharedMemorySize, SMEM_ATTN);

    dim3 gD(D_MODEL / BN, NTOK / BM);
    dim3 gF(DFF_ / BN,   NTOK / BM);
    dim3 gA(LT_ / AT, NH, B_);

    // ---- sublayer 1: self-attention (pre-norm) ----
    ln_kernel<<<NTOK, 256>>>(tgt, ln1_g, ln1_b, ln);
    sgemm_kernel<<<gD, 256>>>(ln, self_wq, self_bq, nullptr, q,  NTOK, D_MODEL, D_MODEL, 0);
    sgemm_kernel<<<gD, 256>>>(ln, self_wk, self_bk, nullptr, k,  NTOK, D_MODEL, D_MODEL, 0);
    sgemm_kernel<<<gD, 256>>>(ln, self_wv, self_bv, nullptr, v,  NTOK, D_MODEL, D_MODEL, 0);
    attn_tile_kernel<<<gA, 256, SMEM_ATTN>>>(q, k, v, nullptr, ctx, LT_, LT_, 1);
    sgemm_kernel<<<gD, 256>>>(ctx, self_wo, self_bo, tgt, x1, NTOK, D_MODEL, D_MODEL, 0);

    // ---- sublayer 2: cross-attention (pre-norm; K/V from raw memory) ----
    ln_kernel<<<NTOK, 256>>>(x1, ln2_g, ln2_b, ln);
    sgemm_kernel<<<gD, 256>>>(ln,     cross_wq, cross_bq, nullptr, q, NTOK, D_MODEL, D_MODEL, 0);
    sgemm_kernel<<<gD, 256>>>(memory, cross_wk, cross_bk, nullptr, k, NTOK, D_MODEL, D_MODEL, 0);
    sgemm_kernel<<<gD, 256>>>(memory, cross_wv, cross_bv, nullptr, v, NTOK, D_MODEL, D_MODEL, 0);
    attn_tile_kernel<<<gA, 256, SMEM_ATTN>>>(q, k, v, src_pad, ctx, LT_, LS_, 0);
    sgemm_kernel<<<gD, 256>>>(ctx, cross_wo, cross_bo, x1, x2, NTOK, D_MODEL, D_MODEL, 0);

    // ---- sublayer 3: FFN (pre-norm) ----
    ln_kernel<<<NTOK, 256>>>(x2, ln3_g, ln3_b, ln);
    sgemm_kernel<<<gF, 256>>>(ln,  ffn_w1, ffn_b1, nullptr, ffn, NTOK, DFF_,    D_MODEL, 1);
    sgemm_kernel<<<gD, 256>>>(ffn, ffn_w2, ffn_b2, x2, out,      NTOK, D_MODEL, DFF_,    0);
}

// round 4
// speedup vs baseline: 7.6547x; 2.9622x over previous
#include <cuda_runtime.h>
#include <cuda_fp16.h>
#include <math.h>

// ---------------- problem constants ----------------
#define D_MODEL 1024
#define NH      16
#define DK_     64
#define DFF_    4096
#define B_      4
#define LT_     1024
#define LS_     1024
#define NTOK    (B_ * LT_)   // 4096 rows

// ---------------- scratch (static device globals; no allocs allowed) -------
__device__ float  g_q  [NTOK * D_MODEL];
__device__ float  g_k  [NTOK * D_MODEL];
__device__ float  g_v  [NTOK * D_MODEL];
__device__ float  g_x1 [NTOK * D_MODEL];
__device__ float  g_x2 [NTOK * D_MODEL];
__device__ __half g_ln16 [NTOK * D_MODEL];
__device__ __half g_ctx16[NTOK * D_MODEL];
__device__ __half g_mem16[NTOK * D_MODEL];
__device__ __half g_ffn16[NTOK * DFF_];
// weight pool: 8 x (1024x1024) + 2 x (1024x4096) = 16M halfs
__device__ __half g_w16[8 * D_MODEL * D_MODEL + 2 * D_MODEL * DFF_];

// ---------------- fp32 -> fp16 convert -------------------------------------
__global__ void f2h_kernel(const float* __restrict__ x, __half* __restrict__ y, int n) {
    int i = (blockIdx.x * blockDim.x + threadIdx.x) << 3;
    if (i >= n) return;
    float4 a = *(const float4*)&x[i];
    float4 b = *(const float4*)&x[i + 4];
    __half2 h0 = __floats2half2_rn(a.x, a.y), h1 = __floats2half2_rn(a.z, a.w);
    __half2 h2 = __floats2half2_rn(b.x, b.y), h3 = __floats2half2_rn(b.z, b.w);
    uint4 o;
    o.x = *(unsigned*)&h0; o.y = *(unsigned*)&h1;
    o.z = *(unsigned*)&h2; o.w = *(unsigned*)&h3;
    *(uint4*)&y[i] = o;
}

// ---------------- LayerNorm: fp32 in, fp16 out -----------------------------
__global__ void ln_kernel(const float* __restrict__ x, const float* __restrict__ g,
                          const float* __restrict__ b, __half* __restrict__ y) {
    int row = blockIdx.x;
    const float* xr = x + (size_t)row * D_MODEL;
    __half*      yr = y + (size_t)row * D_MODEL;
    int t = threadIdx.x;

    float4 v = *(const float4*)&xr[t * 4];
    float s  = v.x + v.y + v.z + v.w;
    float ss = v.x * v.x + v.y * v.y + v.z * v.z + v.w * v.w;

    #pragma unroll
    for (int o = 16; o; o >>= 1) {
        s  += __shfl_xor_sync(0xffffffffu, s,  o);
        ss += __shfl_xor_sync(0xffffffffu, ss, o);
    }
    __shared__ float rs[8], rss[8];
    int w = t >> 5, lane = t & 31;
    if (lane == 0) { rs[w] = s; rss[w] = ss; }
    __syncthreads();
    float tot = 0.f, tot2 = 0.f;
    #pragma unroll
    for (int i = 0; i < 8; i++) { tot += rs[i]; tot2 += rss[i]; }

    float mu  = tot * (1.0f / D_MODEL);
    float var = tot2 * (1.0f / D_MODEL) - mu * mu;
    float r   = rsqrtf(var + 1e-5f);

    float4 gv = *(const float4*)&g[t * 4];
    float4 bv = *(const float4*)&b[t * 4];
    __half2 h0 = __floats2half2_rn((v.x - mu) * r * gv.x + bv.x,
                                   (v.y - mu) * r * gv.y + bv.y);
    __half2 h1 = __floats2half2_rn((v.z - mu) * r * gv.z + bv.z,
                                   (v.w - mu) * r * gv.w + bv.w);
    uint2 o; o.x = *(unsigned*)&h0; o.y = *(unsigned*)&h1;
    *(uint2*)&yr[t * 4] = o;
}

// ---------------- GELU (tanh approximation) --------------------------------
__device__ __forceinline__ float gelu_f(float x) {
    float x3 = x * x * x;
    float t  = tanhf(0.7978845608028654f * (x + 0.044715f * x3));
    return 0.5f * x * (1.0f + t);
}

// ---------------- HGEMM: C[M,N] = A[M,K]h @ W[K,N]h + bias (+res)(gelu) ----
// BM=BN=128, BK=32, 256 thr = 8 warps (4 along M x 2 along N, warp 32x64).
// cp.async double buffer, ldmatrix + mma.sync.m16n8k16 f32.f16.f16.f32.
#define HBK  32
#define ASTR 40     // 32 + 8 halfs pad: 80B row stride (16B aligned, conflict-free)
#define BSTR 136    // 128 + 8 halfs pad: 272B row stride

__device__ __forceinline__ unsigned smem_u32(const void* p) {
    return (unsigned)__cvta_generic_to_shared(p);
}

__global__ __launch_bounds__(256, 2)
void hgemm_kernel(const __half* __restrict__ A, const __half* __restrict__ W,
                  const float* __restrict__ bias, const float* __restrict__ residual,
                  void* __restrict__ Cout, int M, int N, int K,
                  int do_gelu, int out_half) {
    __shared__ __half As[2][128 * ASTR];
    __shared__ __half Bs[2][HBK * BSTR];

    const int tid  = threadIdx.x;
    const int wid  = tid >> 5, lane = tid & 31;
    const int wm   = (wid & 3) << 5;   // warp row offset (0,32,64,96)
    const int wn   = (wid >> 2) << 6;  // warp col offset (0,64)
    const int row0 = blockIdx.y << 7;
    const int col0 = blockIdx.x << 7;

    // cp.async chunk mapping (16B = 8 halfs per chunk, 512 chunks per tile)
    const int ar0 = tid >> 2,         ac0 = (tid & 3) << 3;
    const int ar1 = (tid + 256) >> 2, ac1 = ((tid + 256) & 3) << 3;
    const int br0 = tid >> 4,         bc0 = (tid & 15) << 3;
    const int br1 = (tid + 256) >> 4, bc1 = ((tid + 256) & 15) << 3;

    float acc[2][8][4];
    #pragma unroll
    for (int i = 0; i < 2; i++)
        #pragma unroll
        for (int j = 0; j < 8; j++)
            #pragma unroll
            for (int x = 0; x < 4; x++) acc[i][j][x] = 0.f;

    const int KT = K / HBK;

    #define LOAD_TILES(kt, buf) do {                                               \
        int k0 = (kt) * HBK;                                                       \
        unsigned d0 = smem_u32(&As[buf][ar0 * ASTR + ac0]);                        \
        asm volatile("cp.async.cg.shared.global [%0], [%1], 16;" ::                \
            "r"(d0), "l"(&A[(size_t)(row0 + ar0) * K + k0 + ac0]));                \
        unsigned d1 = smem_u32(&As[buf][ar1 * ASTR + ac1]);                        \
        asm volatile("cp.async.cg.shared.global [%0], [%1], 16;" ::                \
            "r"(d1), "l"(&A[(size_t)(row0 + ar1) * K + k0 + ac1]));                \
        unsigned d2 = smem_u32(&Bs[buf][br0 * BSTR + bc0]);                        \
        asm volatile("cp.async.cg.shared.global [%0], [%1], 16;" ::                \
            "r"(d2), "l"(&W[(size_t)(k0 + br0) * N + col0 + bc0]));                \
        unsigned d3 = smem_u32(&Bs[buf][br1 * BSTR + bc1]);                        \
        asm volatile("cp.async.cg.shared.global [%0], [%1], 16;" ::                \
            "r"(d3), "l"(&W[(size_t)(k0 + br1) * N + col0 + bc1]));                \
        asm volatile("cp.async.commit_group;");                                    \
    } while (0)

    LOAD_TILES(0, 0);

    for (int kt = 0; kt < KT; kt++) {
        const int buf = kt & 1;
        if (kt + 1 < KT) {
            LOAD_TILES(kt + 1, buf ^ 1);
            asm volatile("cp.async.wait_group 1;");
        } else {
            asm volatile("cp.async.wait_group 0;");
        }
        __syncthreads();

        #pragma unroll
        for (int ks = 0; ks < 2; ks++) {
            const int kk = ks << 4;
            unsigned a[2][4];
            #pragma unroll
            for (int mt = 0; mt < 2; mt++) {
                int r = wm + (mt << 4) + (lane & 15);
                int c = kk + ((lane >> 4) << 3);
                unsigned addr = smem_u32(&As[buf][r * ASTR + c]);
                asm volatile("ldmatrix.sync.aligned.m8n8.x4.shared.b16 {%0,%1,%2,%3}, [%4];"
                    : "=r"(a[mt][0]), "=r"(a[mt][1]), "=r"(a[mt][2]), "=r"(a[mt][3])
                    : "r"(addr));
            }
            unsigned bf[4][4];
            #pragma unroll
            for (int nq = 0; nq < 4; nq++) {
                int r = kk + (lane & 15);
                int c = wn + (nq << 4) + ((lane >> 4) << 3);
                unsigned addr = smem_u32(&Bs[buf][r * BSTR + c]);
                asm volatile("ldmatrix.sync.aligned.m8n8.x4.trans.shared.b16 {%0,%1,%2,%3}, [%4];"
                    : "=r"(bf[nq][0]), "=r"(bf[nq][1]), "=r"(bf[nq][2]), "=r"(bf[nq][3])
                    : "r"(addr));
            }
            #pragma unroll
            for (int mt = 0; mt < 2; mt++)
                #pragma unroll
                for (int nt = 0; nt < 8; nt++) {
                    asm volatile(
                        "mma.sync.aligned.m16n8k16.row.col.f32.f16.f16.f32 "
                        "{%0,%1,%2,%3}, {%4,%5,%6,%7}, {%8,%9}, {%0,%1,%2,%3};"
                        : "+f"(acc[mt][nt][0]), "+f"(acc[mt][nt][1]),
                          "+f"(acc[mt][nt][2]), "+f"(acc[mt][nt][3])
                        : "r"(a[mt][0]), "r"(a[mt][1]), "r"(a[mt][2]), "r"(a[mt][3]),
                          "r"(bf[nt >> 1][(nt & 1) * 2]), "r"(bf[nt >> 1][(nt & 1) * 2 + 1]));
                }
        }
        __syncthreads();
    }

    // epilogue
    const int lr = lane >> 2;
    const int lc = (lane & 3) << 1;
    #pragma unroll
    for (int mt = 0; mt < 2; mt++) {
        #pragma unroll
        for (int h2 = 0; h2 < 2; h2++) {
            int gr = row0 + wm + (mt << 4) + lr + (h2 << 3);
            #pragma unroll
            for (int nt = 0; nt < 8; nt++) {
                int gc = col0 + wn + (nt << 3) + lc;
                float v0 = acc[mt][nt][h2 * 2 + 0] + bias[gc];
                float v1 = acc[mt][nt][h2 * 2 + 1] + bias[gc + 1];
                if (residual) {
                    float2 rv = *(const float2*)&residual[(size_t)gr * N + gc];
                    v0 += rv.x; v1 += rv.y;
                }
                if (do_gelu) { v0 = gelu_f(v0); v1 = gelu_f(v1); }
                if (out_half) {
                    __half2 hv = __floats2half2_rn(v0, v1);
                    *(__half2*)((__half*)Cout + (size_t)gr * N + gc) = hv;
                } else {
                    float2 ov; ov.x = v0; ov.y = v1;
                    *(float2*)((float*)Cout + (size_t)gr * N + gc) = ov;
                }
            }
        }
    }
}

// ---------------- tiled flash attention (fp32 in, fp16 ctx out) ------------
#define AT 64
#define KST_STRIDE 65
#define SMEM_ATTN ((4096 + 64 * KST_STRIDE + 4096) * 4)

__global__ __launch_bounds__(256)
void attn_tile_kernel(const float* __restrict__ Q, const float* __restrict__ K,
                      const float* __restrict__ V,
                      const unsigned char* __restrict__ mask,
                      __half* __restrict__ O, int Lq, int Lk, int causal) {
    extern __shared__ float sm[];
    float* Qs  = sm;
    float* KsT = sm + 4096;
    float* Ps  = sm + 4096;
    float* Vs  = sm + 4096 + 64 * KST_STRIDE;

    int qt = blockIdx.x;
    int h  = blockIdx.y;
    int b  = blockIdx.z;
    int tid = threadIdx.x, w = tid >> 5, l = tid & 31;
    int q0 = qt * AT;

    const float* Qb = Q + ((size_t)(b * Lq + q0)) * D_MODEL + h * DK_;
    const float* Kb = K + ((size_t)b * Lk) * D_MODEL + h * DK_;
    const float* Vb = V + ((size_t)b * Lk) * D_MODEL + h * DK_;

    #pragma unroll
    for (int p = 0; p < 4; p++) {
        int idx = p * 256 + tid;
        int r = idx >> 4, c4 = (idx & 15) * 4;
        float4 v4 = *(const float4*)&Qb[(size_t)r * D_MODEL + c4];
        v4.x *= 0.125f; v4.y *= 0.125f; v4.z *= 0.125f; v4.w *= 0.125f;
        *(float4*)&Qs[r * 64 + c4] = v4;
    }

    float m_i[8], l_i[8], o0[8], o1[8];
    #pragma unroll
    for (int i = 0; i < 8; i++) { m_i[i] = -3.0e38f; l_i[i] = 0.f; o0[i] = 0.f; o1[i] = 0.f; }

    int ntile = causal ? (qt + 1) : (Lk / AT);

    for (int kt = 0; kt < ntile; kt++) {
        int kg = kt * AT;
        __syncthreads();

        #pragma unroll
        for (int p = 0; p < 4; p++) {
            int idx = p * 256 + tid;
            int r = idx >> 4, c4 = (idx & 15) * 4;
            float4 kv = *(const float4*)&Kb[(size_t)(kg + r) * D_MODEL + c4];
            KsT[(c4 + 0) * KST_STRIDE + r] = kv.x;
            KsT[(c4 + 1) * KST_STRIDE + r] = kv.y;
            KsT[(c4 + 2) * KST_STRIDE + r] = kv.z;
            KsT[(c4 + 3) * KST_STRIDE + r] = kv.w;
            float4 vv = *(const float4*)&Vb[(size_t)(kg + r) * D_MODEL + c4];
            *(float4*)&Vs[r * 64 + c4] = vv;
        }
        __syncthreads();

        float s0[8] = {}, s1[8] = {};
        #pragma unroll
        for (int d0 = 0; d0 < 64; d0 += 4) {
            float ka[4], kb2[4];
            #pragma unroll
            for (int j = 0; j < 4; j++) {
                ka[j]  = KsT[(d0 + j) * KST_STRIDE + l];
                kb2[j] = KsT[(d0 + j) * KST_STRIDE + l + 32];
            }
            #pragma unroll
            for (int i = 0; i < 8; i++) {
                float4 qv = *(const float4*)&Qs[(w * 8 + i) * 64 + d0];
                s0[i] = fmaf(qv.x, ka[0],  s0[i]);
                s0[i] = fmaf(qv.y, ka[1],  s0[i]);
                s0[i] = fmaf(qv.z, ka[2],  s0[i]);
                s0[i] = fmaf(qv.w, ka[3],  s0[i]);
                s1[i] = fmaf(qv.x, kb2[0], s1[i]);
                s1[i] = fmaf(qv.y, kb2[1], s1[i]);
                s1[i] = fmaf(qv.z, kb2[2], s1[i]);
                s1[i] = fmaf(qv.w, kb2[3], s1[i]);
            }
        }

        if (mask) {
            const unsigned char* mb = mask + ((size_t)(b * Lq + q0 + w * 8)) * Lk + kg;
            #pragma unroll
            for (int i = 0; i < 8; i++) {
                if (mb[(size_t)i * Lk + l])      s0[i] = -3.0e38f;
                if (mb[(size_t)i * Lk + l + 32]) s1[i] = -3.0e38f;
            }
        }
        if (causal && kt == qt) {
            #pragma unroll
            for (int i = 0; i < 8; i++) {
                int row = w * 8 + i;
                if (l > row)      s0[i] = -3.0e38f;
                if (l + 32 > row) s1[i] = -3.0e38f;
            }
        }

        __syncthreads();

        #pragma unroll
        for (int i = 0; i < 8; i++) {
            float smax = fmaxf(s0[i], s1[i]);
            #pragma unroll
            for (int o = 16; o; o >>= 1) smax = fmaxf(smax, __shfl_xor_sync(0xffffffffu, smax, o));
            float mn   = fmaxf(m_i[i], smax);
            float corr = __expf(m_i[i] - mn);
            float p0   = __expf(s0[i] - mn);
            float p1   = __expf(s1[i] - mn);
            float ps   = p0 + p1;
            #pragma unroll
            for (int o = 16; o; o >>= 1) ps += __shfl_xor_sync(0xffffffffu, ps, o);
            l_i[i] = l_i[i] * corr + ps;
            m_i[i] = mn;
            o0[i] *= corr; o1[i] *= corr;
            Ps[(w * 8 + i) * 64 + l]      = p0;
            Ps[(w * 8 + i) * 64 + l + 32] = p1;
        }
        __syncwarp();

        #pragma unroll
        for (int k0 = 0; k0 < 64; k0 += 4) {
            float v0[4], v1[4];
            #pragma unroll
            for (int j = 0; j < 4; j++) {
                v0[j] = Vs[(k0 + j) * 64 + l];
                v1[j] = Vs[(k0 + j) * 64 + l + 32];
            }
            #pragma unroll
            for (int i = 0; i < 8; i++) {
                float4 p4 = *(const float4*)&Ps[(w * 8 + i) * 64 + k0];
                o0[i] = fmaf(p4.x, v0[0], o0[i]);
                o0[i] = fmaf(p4.y, v0[1], o0[i]);
                o0[i] = fmaf(p4.z, v0[2], o0[i]);
                o0[i] = fmaf(p4.w, v0[3], o0[i]);
                o1[i] = fmaf(p4.x, v1[0], o1[i]);
                o1[i] = fmaf(p4.y, v1[1], o1[i]);
                o1[i] = fmaf(p4.z, v1[2], o1[i]);
                o1[i] = fmaf(p4.w, v1[3], o1[i]);
            }
        }
    }

    #pragma unroll
    for (int i = 0; i < 8; i++) {
        float inv = 1.0f / l_i[i];
        __half* op = O + ((size_t)(b * Lq + q0 + w * 8 + i)) * D_MODEL + h * DK_;
        op[l]      = __float2half_rn(o0[i] * inv);
        op[l + 32] = __float2half_rn(o1[i] * inv);
    }
}

// ---------------- launch ---------------------------------------------------
extern "C" void kernel_launch(void* const* d_in, const int* in_sizes, int n_in,
                              void* d_out, int out_size) {
    const float* tgt      = (const float*)d_in[0];
    const float* memory   = (const float*)d_in[1];
    const unsigned char* src_pad = (const unsigned char*)d_in[2];
    // d_in[3] = tgt_mask (causal triu) — handled via causal flag
    const float* self_wq  = (const float*)d_in[4];
    const float* self_bq  = (const float*)d_in[5];
    const float* self_wk  = (const float*)d_in[6];
    const float* self_bk  = (const float*)d_in[7];
    const float* self_wv  = (const float*)d_in[8];
    const float* self_bv  = (const float*)d_in[9];
    const float* self_wo  = (const float*)d_in[10];
    const float* self_bo  = (const float*)d_in[11];
    const float* cross_wq = (const float*)d_in[12];
    const float* cross_bq = (const float*)d_in[13];
    const float* cross_wk = (const float*)d_in[14];
    const float* cross_bk = (const float*)d_in[15];
    const float* cross_wv = (const float*)d_in[16];
    const float* cross_bv = (const float*)d_in[17];
    const float* cross_wo = (const float*)d_in[18];
    const float* cross_bo = (const float*)d_in[19];
    const float* ln1_g    = (const float*)d_in[20];
    const float* ln1_b    = (const float*)d_in[21];
    const float* ln2_g    = (const float*)d_in[22];
    const float* ln2_b    = (const float*)d_in[23];
    const float* ln3_g    = (const float*)d_in[24];
    const float* ln3_b    = (const float*)d_in[25];
    const float* ffn_w1   = (const float*)d_in[26];
    const float* ffn_b1   = (const float*)d_in[27];
    const float* ffn_w2   = (const float*)d_in[28];
    const float* ffn_b2   = (const float*)d_in[29];

    float *q, *k, *v, *x1, *x2;
    __half *ln16, *ctx16, *mem16, *ffn16, *w16;
    cudaGetSymbolAddress((void**)&q,     g_q);
    cudaGetSymbolAddress((void**)&k,     g_k);
    cudaGetSymbolAddress((void**)&v,     g_v);
    cudaGetSymbolAddress((void**)&x1,    g_x1);
    cudaGetSymbolAddress((void**)&x2,    g_x2);
    cudaGetSymbolAddress((void**)&ln16,  g_ln16);
    cudaGetSymbolAddress((void**)&ctx16, g_ctx16);
    cudaGetSymbolAddress((void**)&mem16, g_mem16);
    cudaGetSymbolAddress((void**)&ffn16, g_ffn16);
    cudaGetSymbolAddress((void**)&w16,   g_w16);

    const int MM = D_MODEL * D_MODEL;     // 1M
    __half* swq16 = w16 + 0 * MM;
    __half* swk16 = w16 + 1 * MM;
    __half* swv16 = w16 + 2 * MM;
    __half* swo16 = w16 + 3 * MM;
    __half* cwq16 = w16 + 4 * MM;
    __half* cwk16 = w16 + 5 * MM;
    __half* cwv16 = w16 + 6 * MM;
    __half* cwo16 = w16 + 7 * MM;
    __half* w1_16 = w16 + 8 * MM;                    // 4M
    __half* w2_16 = w16 + 8 * MM + D_MODEL * DFF_;   // 4M

    float* out = (float*)d_out;

    cudaFuncSetAttribute(attn_tile_kernel,
                         cudaFuncAttributeMaxDynamicSharedMemorySize, SMEM_ATTN);

    // ---- weight + memory fp16 conversions ----
    const int CT = 256;
    f2h_kernel<<<MM / 8 / CT, CT>>>(self_wq,  swq16, MM);
    f2h_kernel<<<MM / 8 / CT, CT>>>(self_wk,  swk16, MM);
    f2h_kernel<<<MM / 8 / CT, CT>>>(self_wv,  swv16, MM);
    f2h_kernel<<<MM / 8 / CT, CT>>>(self_wo,  swo16, MM);
    f2h_kernel<<<MM / 8 / CT, CT>>>(cross_wq, cwq16, MM);
    f2h_kernel<<<MM / 8 / CT, CT>>>(cross_wk, cwk16, MM);
    f2h_kernel<<<MM / 8 / CT, CT>>>(cross_wv, cwv16, MM);
    f2h_kernel<<<MM / 8 / CT, CT>>>(cross_wo, cwo16, MM);
    f2h_kernel<<<D_MODEL * DFF_ / 8 / CT, CT>>>(ffn_w1, w1_16, D_MODEL * DFF_);
    f2h_kernel<<<D_MODEL * DFF_ / 8 / CT, CT>>>(ffn_w2, w2_16, D_MODEL * DFF_);
    f2h_kernel<<<NTOK * D_MODEL / 8 / CT, CT>>>(memory, mem16, NTOK * D_MODEL);

    dim3 gD(D_MODEL / 128, NTOK / 128);   // (8, 32)
    dim3 gF(DFF_ / 128,    NTOK / 128);   // (32, 32)
    dim3 gA(LT_ / AT, NH, B_);

    // ---- sublayer 1: self-attention (pre-norm) ----
    ln_kernel<<<NTOK, 256>>>(tgt, ln1_g, ln1_b, ln16);
    hgemm_kernel<<<gD, 256>>>(ln16, swq16, self_bq, nullptr, q, NTOK, D_MODEL, D_MODEL, 0, 0);
    hgemm_kernel<<<gD, 256>>>(ln16, swk16, self_bk, nullptr, k, NTOK, D_MODEL, D_MODEL, 0, 0);
    hgemm_kernel<<<gD, 256>>>(ln16, swv16, self_bv, nullptr, v, NTOK, D_MODEL, D_MODEL, 0, 0);
    attn_tile_kernel<<<gA, 256, SMEM_ATTN>>>(q, k, v, nullptr, ctx16, LT_, LT_, 1);
    hgemm_kernel<<<gD, 256>>>(ctx16, swo16, self_bo, tgt, x1, NTOK, D_MODEL, D_MODEL, 0, 0);

    // ---- sublayer 2: cross-attention (pre-norm; K/V from raw memory) ----
    ln_kernel<<<NTOK, 256>>>(x1, ln2_g, ln2_b, ln16);
    hgemm_kernel<<<gD, 256>>>(ln16,  cwq16, cross_bq, nullptr, q, NTOK, D_MODEL, D_MODEL, 0, 0);
    hgemm_kernel<<<gD, 256>>>(mem16, cwk16, cross_bk, nullptr, k, NTOK, D_MODEL, D_MODEL, 0, 0);
    hgemm_kernel<<<gD, 256>>>(mem16, cwv16, cross_bv, nullptr, v, NTOK, D_MODEL, D_MODEL, 0, 0);
    attn_tile_kernel<<<gA, 256, SMEM_ATTN>>>(q, k, v, src_pad, ctx16, LT_, LS_, 0);
    hgemm_kernel<<<gD, 256>>>(ctx16, cwo16, cross_bo, x1, x2, NTOK, D_MODEL, D_MODEL, 0, 0);

    // ---- sublayer 3: FFN (pre-norm) ----
    ln_kernel<<<NTOK, 256>>>(x2, ln3_g, ln3_b, ln16);
    hgemm_kernel<<<gF, 256>>>(ln16,  w1_16, ffn_b1, nullptr, ffn16, NTOK, DFF_,    D_MODEL, 1, 1);
    hgemm_kernel<<<gD, 256>>>(ffn16, w2_16, ffn_b2, x2, out,        NTOK, D_MODEL, DFF_,    0, 0);
}

// round 5
// speedup vs baseline: 14.9443x; 1.9523x over previous
#include <cuda_runtime.h>
#include <cuda_fp16.h>
#include <math.h>

// ---------------- problem constants ----------------
#define D_MODEL 1024
#define NH      16
#define DK_     64
#define DFF_    4096
#define B_      4
#define LT_     1024
#define LS_     1024
#define NTOK    (B_ * LT_)   // 4096 rows

// ---------------- scratch (static device globals; no allocs allowed) -------
__device__ float  g_x1 [NTOK * D_MODEL];
__device__ float  g_x2 [NTOK * D_MODEL];
__device__ __half g_q16 [NTOK * D_MODEL];
__device__ __half g_k16 [NTOK * D_MODEL];
__device__ __half g_v16 [NTOK * D_MODEL];
__device__ __half g_ln16 [NTOK * D_MODEL];
__device__ __half g_ctx16[NTOK * D_MODEL];
__device__ __half g_mem16[NTOK * D_MODEL];
__device__ __half g_ffn16[NTOK * DFF_];
// weight pool: 8 x (1024x1024) + 2 x (1024x4096) = 16M halfs
__device__ __half g_w16[8 * D_MODEL * D_MODEL + 2 * D_MODEL * DFF_];

// ---------------- fp32 -> fp16 convert -------------------------------------
__global__ void f2h_kernel(const float* __restrict__ x, __half* __restrict__ y, int n) {
    int i = (blockIdx.x * blockDim.x + threadIdx.x) << 3;
    if (i >= n) return;
    float4 a = *(const float4*)&x[i];
    float4 b = *(const float4*)&x[i + 4];
    __half2 h0 = __floats2half2_rn(a.x, a.y), h1 = __floats2half2_rn(a.z, a.w);
    __half2 h2 = __floats2half2_rn(b.x, b.y), h3 = __floats2half2_rn(b.z, b.w);
    uint4 o;
    o.x = *(unsigned*)&h0; o.y = *(unsigned*)&h1;
    o.z = *(unsigned*)&h2; o.w = *(unsigned*)&h3;
    *(uint4*)&y[i] = o;
}

// ---------------- LayerNorm: fp32 in, fp16 out -----------------------------
__global__ void ln_kernel(const float* __restrict__ x, const float* __restrict__ g,
                          const float* __restrict__ b, __half* __restrict__ y) {
    int row = blockIdx.x;
    const float* xr = x + (size_t)row * D_MODEL;
    __half*      yr = y + (size_t)row * D_MODEL;
    int t = threadIdx.x;

    float4 v = *(const float4*)&xr[t * 4];
    float s  = v.x + v.y + v.z + v.w;
    float ss = v.x * v.x + v.y * v.y + v.z * v.z + v.w * v.w;

    #pragma unroll
    for (int o = 16; o; o >>= 1) {
        s  += __shfl_xor_sync(0xffffffffu, s,  o);
        ss += __shfl_xor_sync(0xffffffffu, ss, o);
    }
    __shared__ float rs[8], rss[8];
    int w = t >> 5, lane = t & 31;
    if (lane == 0) { rs[w] = s; rss[w] = ss; }
    __syncthreads();
    float tot = 0.f, tot2 = 0.f;
    #pragma unroll
    for (int i = 0; i < 8; i++) { tot += rs[i]; tot2 += rss[i]; }

    float mu  = tot * (1.0f / D_MODEL);
    float var = tot2 * (1.0f / D_MODEL) - mu * mu;
    float r   = rsqrtf(var + 1e-5f);

    float4 gv = *(const float4*)&g[t * 4];
    float4 bv = *(const float4*)&b[t * 4];
    __half2 h0 = __floats2half2_rn((v.x - mu) * r * gv.x + bv.x,
                                   (v.y - mu) * r * gv.y + bv.y);
    __half2 h1 = __floats2half2_rn((v.z - mu) * r * gv.z + bv.z,
                                   (v.w - mu) * r * gv.w + bv.w);
    uint2 o; o.x = *(unsigned*)&h0; o.y = *(unsigned*)&h1;
    *(uint2*)&yr[t * 4] = o;
}

// ---------------- GELU (tanh approximation) --------------------------------
__device__ __forceinline__ float gelu_f(float x) {
    float x3 = x * x * x;
    float t  = tanhf(0.7978845608028654f * (x + 0.044715f * x3));
    return 0.5f * x * (1.0f + t);
}

__device__ __forceinline__ unsigned smem_u32(const void* p) {
    return (unsigned)__cvta_generic_to_shared(p);
}

__device__ __forceinline__ void mma_16816(float* c, const unsigned* a,
                                          unsigned b0, unsigned b1) {
    asm volatile(
        "mma.sync.aligned.m16n8k16.row.col.f32.f16.f16.f32 "
        "{%0,%1,%2,%3}, {%4,%5,%6,%7}, {%8,%9}, {%0,%1,%2,%3};"
        : "+f"(c[0]), "+f"(c[1]), "+f"(c[2]), "+f"(c[3])
        : "r"(a[0]), "r"(a[1]), "r"(a[2]), "r"(a[3]), "r"(b0), "r"(b1));
}

// ---------------- HGEMM: C[M,N] = A[M,K]h @ W[K,N]h + bias (+res)(gelu) ----
#define HBK  32
#define ASTR 40
#define BSTR 136

__global__ __launch_bounds__(256, 2)
void hgemm_kernel(const __half* __restrict__ A, const __half* __restrict__ W,
                  const float* __restrict__ bias, const float* __restrict__ residual,
                  void* __restrict__ Cout, int M, int N, int K,
                  int do_gelu, int out_half) {
    __shared__ __half As[2][128 * ASTR];
    __shared__ __half Bs[2][HBK * BSTR];

    const int tid  = threadIdx.x;
    const int wid  = tid >> 5, lane = tid & 31;
    const int wm   = (wid & 3) << 5;
    const int wn   = (wid >> 2) << 6;
    const int row0 = blockIdx.y << 7;
    const int col0 = blockIdx.x << 7;

    const int ar0 = tid >> 2,         ac0 = (tid & 3) << 3;
    const int ar1 = (tid + 256) >> 2, ac1 = ((tid + 256) & 3) << 3;
    const int br0 = tid >> 4,         bc0 = (tid & 15) << 3;
    const int br1 = (tid + 256) >> 4, bc1 = ((tid + 256) & 15) << 3;

    float acc[2][8][4];
    #pragma unroll
    for (int i = 0; i < 2; i++)
        #pragma unroll
        for (int j = 0; j < 8; j++)
            #pragma unroll
            for (int x = 0; x < 4; x++) acc[i][j][x] = 0.f;

    const int KT = K / HBK;

    #define LOAD_TILES(kt, buf) do {                                               \
        int k0 = (kt) * HBK;                                                       \
        unsigned d0 = smem_u32(&As[buf][ar0 * ASTR + ac0]);                        \
        asm volatile("cp.async.cg.shared.global [%0], [%1], 16;" ::                \
            "r"(d0), "l"(&A[(size_t)(row0 + ar0) * K + k0 + ac0]));                \
        unsigned d1 = smem_u32(&As[buf][ar1 * ASTR + ac1]);                        \
        asm volatile("cp.async.cg.shared.global [%0], [%1], 16;" ::                \
            "r"(d1), "l"(&A[(size_t)(row0 + ar1) * K + k0 + ac1]));                \
        unsigned d2 = smem_u32(&Bs[buf][br0 * BSTR + bc0]);                        \
        asm volatile("cp.async.cg.shared.global [%0], [%1], 16;" ::                \
            "r"(d2), "l"(&W[(size_t)(k0 + br0) * N + col0 + bc0]));                \
        unsigned d3 = smem_u32(&Bs[buf][br1 * BSTR + bc1]);                        \
        asm volatile("cp.async.cg.shared.global [%0], [%1], 16;" ::                \
            "r"(d3), "l"(&W[(size_t)(k0 + br1) * N + col0 + bc1]));                \
        asm volatile("cp.async.commit_group;");                                    \
    } while (0)

    LOAD_TILES(0, 0);

    for (int kt = 0; kt < KT; kt++) {
        const int buf = kt & 1;
        if (kt + 1 < KT) {
            LOAD_TILES(kt + 1, buf ^ 1);
            asm volatile("cp.async.wait_group 1;");
        } else {
            asm volatile("cp.async.wait_group 0;");
        }
        __syncthreads();

        #pragma unroll
        for (int ks = 0; ks < 2; ks++) {
            const int kk = ks << 4;
            unsigned a[2][4];
            #pragma unroll
            for (int mt = 0; mt < 2; mt++) {
                int r = wm + (mt << 4) + (lane & 15);
                int c = kk + ((lane >> 4) << 3);
                unsigned addr = smem_u32(&As[buf][r * ASTR + c]);
                asm volatile("ldmatrix.sync.aligned.m8n8.x4.shared.b16 {%0,%1,%2,%3}, [%4];"
                    : "=r"(a[mt][0]), "=r"(a[mt][1]), "=r"(a[mt][2]), "=r"(a[mt][3])
                    : "r"(addr));
            }
            unsigned bf[4][4];
            #pragma unroll
            for (int nq = 0; nq < 4; nq++) {
                int r = kk + (lane & 15);
                int c = wn + (nq << 4) + ((lane >> 4) << 3);
                unsigned addr = smem_u32(&Bs[buf][r * BSTR + c]);
                asm volatile("ldmatrix.sync.aligned.m8n8.x4.trans.shared.b16 {%0,%1,%2,%3}, [%4];"
                    : "=r"(bf[nq][0]), "=r"(bf[nq][1]), "=r"(bf[nq][2]), "=r"(bf[nq][3])
                    : "r"(addr));
            }
            #pragma unroll
            for (int mt = 0; mt < 2; mt++)
                #pragma unroll
                for (int nt = 0; nt < 8; nt++)
                    mma_16816(acc[mt][nt], a[mt],
                              bf[nt >> 1][(nt & 1) * 2], bf[nt >> 1][(nt & 1) * 2 + 1]);
        }
        __syncthreads();
    }

    const int lr = lane >> 2;
    const int lc = (lane & 3) << 1;
    #pragma unroll
    for (int mt = 0; mt < 2; mt++) {
        #pragma unroll
        for (int h2 = 0; h2 < 2; h2++) {
            int gr = row0 + wm + (mt << 4) + lr + (h2 << 3);
            #pragma unroll
            for (int nt = 0; nt < 8; nt++) {
                int gc = col0 + wn + (nt << 3) + lc;
                float v0 = acc[mt][nt][h2 * 2 + 0] + bias[gc];
                float v1 = acc[mt][nt][h2 * 2 + 1] + bias[gc + 1];
                if (residual) {
                    float2 rv = *(const float2*)&residual[(size_t)gr * N + gc];
                    v0 += rv.x; v1 += rv.y;
                }
                if (do_gelu) { v0 = gelu_f(v0); v1 = gelu_f(v1); }
                if (out_half) {
                    __half2 hv = __floats2half2_rn(v0, v1);
                    *(__half2*)((__half*)Cout + (size_t)gr * N + gc) = hv;
                } else {
                    float2 ov; ov.x = v0; ov.y = v1;
                    *(float2*)((float*)Cout + (size_t)gr * N + gc) = ov;
                }
            }
        }
    }
}

// ---------------- tensor-core flash attention -------------------------------
// Block: 64 q-rows of one (b,h). 128 threads = 4 warps; warp w owns rows
// [w*16, w*16+16). KV tiles of 64. S = Q K^T and O += P V via m16n8k16 HMMA.
#define QSTR 72   // 64 + 8 halfs pad

__global__ __launch_bounds__(128)
void attn_mma_kernel(const __half* __restrict__ Q, const __half* __restrict__ K,
                     const __half* __restrict__ V,
                     const unsigned char* __restrict__ mask,
                     __half* __restrict__ O, int Lq, int Lk, int causal) {
    __shared__ __half Qs[64][QSTR];
    __shared__ __half Ks[64][QSTR];
    __shared__ __half Vs[64][QSTR];
    __shared__ unsigned char Ms[64][64];

    const int qt = blockIdx.x, h = blockIdx.y, b = blockIdx.z;
    const int tid = threadIdx.x, w = tid >> 5, lane = tid & 31;
    const int q0 = qt * 64;
    const int lr = lane >> 2;          // 0..7
    const int qq = (lane & 3) << 1;    // 0,2,4,6

    const __half* Qb = Q + ((size_t)(b * Lq + q0)) * D_MODEL + h * DK_;
    const __half* Kb = K + ((size_t)b * Lk) * D_MODEL + h * DK_;
    const __half* Vb = V + ((size_t)b * Lk) * D_MODEL + h * DK_;

    // ---- load Q tile, scaled by 1/8 (exact in fp16) ----
    const __half2 qscale = __float2half2_rn(0.125f);
    #pragma unroll
    for (int p = 0; p < 4; p++) {
        int idx = p * 128 + tid;
        int r = idx >> 3, c8 = (idx & 7) << 3;
        uint4 d = *(const uint4*)&Qb[(size_t)r * D_MODEL + c8];
        __half2* hp = (__half2*)&d;
        #pragma unroll
        for (int j = 0; j < 4; j++) hp[j] = __hmul2(hp[j], qscale);
        *(uint4*)&Qs[r][c8] = d;
    }
    __syncthreads();

    // ---- hoist Q fragments (constant across KV tiles) ----
    unsigned qf[4][4];
    #pragma unroll
    for (int kc = 0; kc < 4; kc++) {
        int r = w * 16 + (lane & 15);
        int c = kc * 16 + ((lane >> 4) << 3);
        unsigned addr = smem_u32(&Qs[r][c]);
        asm volatile("ldmatrix.sync.aligned.m8n8.x4.shared.b16 {%0,%1,%2,%3}, [%4];"
            : "=r"(qf[kc][0]), "=r"(qf[kc][1]), "=r"(qf[kc][2]), "=r"(qf[kc][3])
            : "r"(addr));
    }

    float o[8][4];
    #pragma unroll
    for (int i = 0; i < 8; i++)
        #pragma unroll
        for (int j = 0; j < 4; j++) o[i][j] = 0.f;
    float mrow[2] = {-1e30f, -1e30f}, lrow[2] = {0.f, 0.f};

    const int ntile = causal ? (qt + 1) : (Lk / 64);

    for (int kt = 0; kt < ntile; kt++) {
        const int kg = kt * 64;
        __syncthreads();   // previous iteration done with Ks/Vs/Ms

        // ---- load K, V (+ mask) tiles ----
        #pragma unroll
        for (int p = 0; p < 4; p++) {
            int idx = p * 128 + tid;
            int r = idx >> 3, c8 = (idx & 7) << 3;
            *(uint4*)&Ks[r][c8] = *(const uint4*)&Kb[(size_t)(kg + r) * D_MODEL + c8];
            *(uint4*)&Vs[r][c8] = *(const uint4*)&Vb[(size_t)(kg + r) * D_MODEL + c8];
        }
        if (mask) {
            #pragma unroll
            for (int p = 0; p < 2; p++) {
                int idx = p * 128 + tid;
                int r = idx >> 2, ch = (idx & 3) << 4;
                *(uint4*)&Ms[r][ch] =
                    *(const uint4*)(mask + ((size_t)(b * Lq + q0 + r)) * Lk + kg + ch);
            }
        }
        __syncthreads();

        // ---- S = Q K^T ----
        float s[8][4];
        #pragma unroll
        for (int i = 0; i < 8; i++)
            #pragma unroll
            for (int j = 0; j < 4; j++) s[i][j] = 0.f;

        #pragma unroll
        for (int kc = 0; kc < 4; kc++) {
            #pragma unroll
            for (int np = 0; np < 4; np++) {
                unsigned kf[4];
                int r = np * 16 + (lane & 15);
                int c = kc * 16 + ((lane >> 4) << 3);
                unsigned addr = smem_u32(&Ks[r][c]);
                asm volatile("ldmatrix.sync.aligned.m8n8.x4.shared.b16 {%0,%1,%2,%3}, [%4];"
                    : "=r"(kf[0]), "=r"(kf[1]), "=r"(kf[2]), "=r"(kf[3])
                    : "r"(addr));
                mma_16816(s[2 * np],     qf[kc], kf[0], kf[2]);
                mma_16816(s[2 * np + 1], qf[kc], kf[1], kf[3]);
            }
        }

        // ---- masking ----
        if (mask) {
            int r0 = w * 16 + lr, r1 = r0 + 8;
            #pragma unroll
            for (int nt = 0; nt < 8; nt++) {
                int c0 = nt * 8 + qq;
                if (Ms[r0][c0])     s[nt][0] = -3.0e38f;
                if (Ms[r0][c0 + 1]) s[nt][1] = -3.0e38f;
                if (Ms[r1][c0])     s[nt][2] = -3.0e38f;
                if (Ms[r1][c0 + 1]) s[nt][3] = -3.0e38f;
            }
        }
        if (causal && kt == qt) {
            int r0 = w * 16 + lr, r1 = r0 + 8;   // kg == q0: local compare
            #pragma unroll
            for (int nt = 0; nt < 8; nt++) {
                int c0 = nt * 8 + qq;
                if (c0 > r0)     s[nt][0] = -3.0e38f;
                if (c0 + 1 > r0) s[nt][1] = -3.0e38f;
                if (c0 > r1)     s[nt][2] = -3.0e38f;
                if (c0 + 1 > r1) s[nt][3] = -3.0e38f;
            }
        }

        // ---- online softmax (fragment level, quad reductions) ----
        #pragma unroll
        for (int r = 0; r < 2; r++) {
            float mx = -3.0e38f;
            #pragma unroll
            for (int nt = 0; nt < 8; nt++)
                mx = fmaxf(mx, fmaxf(s[nt][2 * r], s[nt][2 * r + 1]));
            mx = fmaxf(mx, __shfl_xor_sync(0xffffffffu, mx, 1));
            mx = fmaxf(mx, __shfl_xor_sync(0xffffffffu, mx, 2));
            float mn   = fmaxf(mrow[r], mx);
            float corr = __expf(mrow[r] - mn);
            mrow[r] = mn;
            float ls = 0.f;
            #pragma unroll
            for (int nt = 0; nt < 8; nt++) {
                s[nt][2 * r]     = __expf(s[nt][2 * r]     - mn);
                s[nt][2 * r + 1] = __expf(s[nt][2 * r + 1] - mn);
                ls += s[nt][2 * r] + s[nt][2 * r + 1];
            }
            ls += __shfl_xor_sync(0xffffffffu, ls, 1);
            ls += __shfl_xor_sync(0xffffffffu, ls, 2);
            lrow[r] = lrow[r] * corr + ls;
            #pragma unroll
            for (int nt = 0; nt < 8; nt++) {
                o[nt][2 * r]     *= corr;
                o[nt][2 * r + 1] *= corr;
            }
        }

        // ---- O += P V  (P: C-frag -> A-frag repack) ----
        #pragma unroll
        for (int kc = 0; kc < 4; kc++) {
            unsigned pa[4];
            __half2 t0 = __floats2half2_rn(s[2 * kc][0],     s[2 * kc][1]);
            __half2 t1 = __floats2half2_rn(s[2 * kc][2],     s[2 * kc][3]);
            __half2 t2 = __floats2half2_rn(s[2 * kc + 1][0], s[2 * kc + 1][1]);
            __half2 t3 = __floats2half2_rn(s[2 * kc + 1][2], s[2 * kc + 1][3]);
            pa[0] = *(unsigned*)&t0; pa[1] = *(unsigned*)&t1;
            pa[2] = *(unsigned*)&t2; pa[3] = *(unsigned*)&t3;
            #pragma unroll
            for (int nd = 0; nd < 4; nd++) {
                unsigned vf[4];
                int r = kc * 16 + (lane & 15);
                int c = nd * 16 + ((lane >> 4) << 3);
                unsigned addr = smem_u32(&Vs[r][c]);
                asm volatile("ldmatrix.sync.aligned.m8n8.x4.trans.shared.b16 {%0,%1,%2,%3}, [%4];"
                    : "=r"(vf[0]), "=r"(vf[1]), "=r"(vf[2]), "=r"(vf[3])
                    : "r"(addr));
                mma_16816(o[2 * nd],     pa, vf[0], vf[1]);
                mma_16816(o[2 * nd + 1], pa, vf[2], vf[3]);
            }
        }
    }

    // ---- epilogue ----
    #pragma unroll
    for (int r = 0; r < 2; r++) {
        float inv = 1.0f / lrow[r];
        int row = q0 + w * 16 + lr + r * 8;
        __half* op = O + (size_t)(b * Lq + row) * D_MODEL + h * DK_;
        #pragma unroll
        for (int nt = 0; nt < 8; nt++) {
            int col = nt * 8 + qq;
            __half2 hv = __floats2half2_rn(o[nt][2 * r] * inv, o[nt][2 * r + 1] * inv);
            *(__half2*)&op[col] = hv;
        }
    }
}

// ---------------- launch ---------------------------------------------------
extern "C" void kernel_launch(void* const* d_in, const int* in_sizes, int n_in,
                              void* d_out, int out_size) {
    const float* tgt      = (const float*)d_in[0];
    const float* memory   = (const float*)d_in[1];
    const unsigned char* src_pad = (const unsigned char*)d_in[2];
    // d_in[3] = tgt_mask (causal triu) — handled via causal flag
    const float* self_wq  = (const float*)d_in[4];
    const float* self_bq  = (const float*)d_in[5];
    const float* self_wk  = (const float*)d_in[6];
    const float* self_bk  = (const float*)d_in[7];
    const float* self_wv  = (const float*)d_in[8];
    const float* self_bv  = (const float*)d_in[9];
    const float* self_wo  = (const float*)d_in[10];
    const float* self_bo  = (const float*)d_in[11];
    const float* cross_wq = (const float*)d_in[12];
    const float* cross_bq = (const float*)d_in[13];
    const float* cross_wk = (const float*)d_in[14];
    const float* cross_bk = (const float*)d_in[15];
    const float* cross_wv = (const float*)d_in[16];
    const float* cross_bv = (const float*)d_in[17];
    const float* cross_wo = (const float*)d_in[18];
    const float* cross_bo = (const float*)d_in[19];
    const float* ln1_g    = (const float*)d_in[20];
    const float* ln1_b    = (const float*)d_in[21];
    const float* ln2_g    = (const float*)d_in[22];
    const float* ln2_b    = (const float*)d_in[23];
    const float* ln3_g    = (const float*)d_in[24];
    const float* ln3_b    = (const float*)d_in[25];
    const float* ffn_w1   = (const float*)d_in[26];
    const float* ffn_b1   = (const float*)d_in[27];
    const float* ffn_w2   = (const float*)d_in[28];
    const float* ffn_b2   = (const float*)d_in[29];

    float *x1, *x2;
    __half *q16, *k16, *v16, *ln16, *ctx16, *mem16, *ffn16, *w16;
    cudaGetSymbolAddress((void**)&x1,    g_x1);
    cudaGetSymbolAddress((void**)&x2,    g_x2);
    cudaGetSymbolAddress((void**)&q16,   g_q16);
    cudaGetSymbolAddress((void**)&k16,   g_k16);
    cudaGetSymbolAddress((void**)&v16,   g_v16);
    cudaGetSymbolAddress((void**)&ln16,  g_ln16);
    cudaGetSymbolAddress((void**)&ctx16, g_ctx16);
    cudaGetSymbolAddress((void**)&mem16, g_mem16);
    cudaGetSymbolAddress((void**)&ffn16, g_ffn16);
    cudaGetSymbolAddress((void**)&w16,   g_w16);

    const int MM = D_MODEL * D_MODEL;
    __half* swq16 = w16 + 0 * MM;
    __half* swk16 = w16 + 1 * MM;
    __half* swv16 = w16 + 2 * MM;
    __half* swo16 = w16 + 3 * MM;
    __half* cwq16 = w16 + 4 * MM;
    __half* cwk16 = w16 + 5 * MM;
    __half* cwv16 = w16 + 6 * MM;
    __half* cwo16 = w16 + 7 * MM;
    __half* w1_16 = w16 + 8 * MM;
    __half* w2_16 = w16 + 8 * MM + D_MODEL * DFF_;

    float* out = (float*)d_out;

    // ---- weight + memory fp16 conversions ----
    const int CT = 256;
    f2h_kernel<<<MM / 8 / CT, CT>>>(self_wq,  swq16, MM);
    f2h_kernel<<<MM / 8 / CT, CT>>>(self_wk,  swk16, MM);
    f2h_kernel<<<MM / 8 / CT, CT>>>(self_wv,  swv16, MM);
    f2h_kernel<<<MM / 8 / CT, CT>>>(self_wo,  swo16, MM);
    f2h_kernel<<<MM / 8 / CT, CT>>>(cross_wq, cwq16, MM);
    f2h_kernel<<<MM / 8 / CT, CT>>>(cross_wk, cwk16, MM);
    f2h_kernel<<<MM / 8 / CT, CT>>>(cross_wv, cwv16, MM);
    f2h_kernel<<<MM / 8 / CT, CT>>>(cross_wo, cwo16, MM);
    f2h_kernel<<<D_MODEL * DFF_ / 8 / CT, CT>>>(ffn_w1, w1_16, D_MODEL * DFF_);
    f2h_kernel<<<D_MODEL * DFF_ / 8 / CT, CT>>>(ffn_w2, w2_16, D_MODEL * DFF_);
    f2h_kernel<<<NTOK * D_MODEL / 8 / CT, CT>>>(memory, mem16, NTOK * D_MODEL);

    dim3 gD(D_MODEL / 128, NTOK / 128);   // (8, 32)
    dim3 gF(DFF_ / 128,    NTOK / 128);   // (32, 32)
    dim3 gA(LT_ / 64, NH, B_);            // (16, 16, 4)

    // ---- sublayer 1: self-attention (pre-norm) ----
    ln_kernel<<<NTOK, 256>>>(tgt, ln1_g, ln1_b, ln16);
    hgemm_kernel<<<gD, 256>>>(ln16, swq16, self_bq, nullptr, q16, NTOK, D_MODEL, D_MODEL, 0, 1);
    hgemm_kernel<<<gD, 256>>>(ln16, swk16, self_bk, nullptr, k16, NTOK, D_MODEL, D_MODEL, 0, 1);
    hgemm_kernel<<<gD, 256>>>(ln16, swv16, self_bv, nullptr, v16, NTOK, D_MODEL, D_MODEL, 0, 1);
    attn_mma_kernel<<<gA, 128>>>(q16, k16, v16, nullptr, ctx16, LT_, LT_, 1);
    hgemm_kernel<<<gD, 256>>>(ctx16, swo16, self_bo, tgt, x1, NTOK, D_MODEL, D_MODEL, 0, 0);

    // ---- sublayer 2: cross-attention (pre-norm; K/V from raw memory) ----
    ln_kernel<<<NTOK, 256>>>(x1, ln2_g, ln2_b, ln16);
    hgemm_kernel<<<gD, 256>>>(ln16,  cwq16, cross_bq, nullptr, q16, NTOK, D_MODEL, D_MODEL, 0, 1);
    hgemm_kernel<<<gD, 256>>>(mem16, cwk16, cross_bk, nullptr, k16, NTOK, D_MODEL, D_MODEL, 0, 1);
    hgemm_kernel<<<gD, 256>>>(mem16, cwv16, cross_bv, nullptr, v16, NTOK, D_MODEL, D_MODEL, 0, 1);
    attn_mma_kernel<<<gA, 128>>>(q16, k16, v16, src_pad, ctx16, LT_, LS_, 0);
    hgemm_kernel<<<gD, 256>>>(ctx16, cwo16, cross_bo, x1, x2, NTOK, D_MODEL, D_MODEL, 0, 0);

    // ---- sublayer 3: FFN (pre-norm) ----
    ln_kernel<<<NTOK, 256>>>(x2, ln3_g, ln3_b, ln16);
    hgemm_kernel<<<gF, 256>>>(ln16,  w1_16, ffn_b1, nullptr, ffn16, NTOK, DFF_,    D_MODEL, 1, 1);
    hgemm_kernel<<<gD, 256>>>(ffn16, w2_16, ffn_b2, x2, out,        NTOK, D_MODEL, DFF_,    0, 0);
}

// round 6
// speedup vs baseline: 16.6498x; 1.1141x over previous
#include <cuda_runtime.h>
#include <cuda_fp16.h>
#include <math.h>

// ---------------- problem constants ----------------
#define D_MODEL 1024
#define NH      16
#define DK_     64
#define DFF_    4096
#define B_      4
#define LT_     1024
#define LS_     1024
#define NTOK    (B_ * LT_)   // 4096 rows

// ---------------- scratch (static device globals; no allocs allowed) -------
__device__ float  g_x1 [NTOK * D_MODEL];
__device__ float  g_x2 [NTOK * D_MODEL];
__device__ __half g_qkv16[NTOK * 3 * D_MODEL];   // self q|k|v fused (ld 3072)
__device__ __half g_q16  [NTOK * D_MODEL];       // cross q
__device__ __half g_kv16 [NTOK * 2 * D_MODEL];   // cross k|v fused (ld 2048)
__device__ __half g_ln16 [NTOK * D_MODEL];
__device__ __half g_ctx16[NTOK * D_MODEL];
__device__ __half g_mem16[NTOK * D_MODEL];
__device__ __half g_ffn16[NTOK * DFF_];
// weight pool: W3(3M) | swo(1M) | cwq(1M) | Wkv(2M) | cwo(1M) | w1(4M) | w2(4M)
__device__ __half g_w16[16 * 1024 * 1024];
__device__ float  g_bias3[3 * D_MODEL];
__device__ float  g_bias2[2 * D_MODEL];

// ---------------- batched fp32 -> fp16 convert (strided dst) ---------------
struct Job { const float* src; __half* dst; int ncols; int dstride; };
struct ConvArgs { Job jobs[11]; long long prefix[12]; };

__global__ void convmany_kernel(ConvArgs a) {
    long long g = ((long long)blockIdx.x * blockDim.x + threadIdx.x) * 8;
    if (g >= a.prefix[11]) return;
    int seg = 0;
    while (g >= a.prefix[seg + 1]) seg++;
    long long off = g - a.prefix[seg];
    Job j = a.jobs[seg];
    int row = (int)(off / j.ncols);
    int col = (int)(off - (long long)row * j.ncols);
    const float* s = j.src + off;
    __half* d = j.dst + (size_t)row * j.dstride + col;
    float4 x0 = *(const float4*)s;
    float4 x1 = *(const float4*)(s + 4);
    __half2 h0 = __floats2half2_rn(x0.x, x0.y), h1 = __floats2half2_rn(x0.z, x0.w);
    __half2 h2 = __floats2half2_rn(x1.x, x1.y), h3 = __floats2half2_rn(x1.z, x1.w);
    uint4 o;
    o.x = *(unsigned*)&h0; o.y = *(unsigned*)&h1;
    o.z = *(unsigned*)&h2; o.w = *(unsigned*)&h3;
    *(uint4*)d = o;
}

__global__ void bias_concat_kernel(const float* b0, const float* b1, const float* b2,
                                   float* d3, const float* c0, const float* c1, float* d2) {
    int t = blockIdx.x * blockDim.x + threadIdx.x;
    if (t < D_MODEL) {
        d3[t] = b0[t]; d3[D_MODEL + t] = b1[t]; d3[2 * D_MODEL + t] = b2[t];
        d2[t] = c0[t]; d2[D_MODEL + t] = c1[t];
    }
}

// ---------------- LayerNorm: fp32 in, fp16 out -----------------------------
__global__ void ln_kernel(const float* __restrict__ x, const float* __restrict__ g,
                          const float* __restrict__ b, __half* __restrict__ y) {
    int row = blockIdx.x;
    const float* xr = x + (size_t)row * D_MODEL;
    __half*      yr = y + (size_t)row * D_MODEL;
    int t = threadIdx.x;

    float4 v = *(const float4*)&xr[t * 4];
    float s  = v.x + v.y + v.z + v.w;
    float ss = v.x * v.x + v.y * v.y + v.z * v.z + v.w * v.w;

    #pragma unroll
    for (int o = 16; o; o >>= 1) {
        s  += __shfl_xor_sync(0xffffffffu, s,  o);
        ss += __shfl_xor_sync(0xffffffffu, ss, o);
    }
    __shared__ float rs[8], rss[8];
    int w = t >> 5, lane = t & 31;
    if (lane == 0) { rs[w] = s; rss[w] = ss; }
    __syncthreads();
    float tot = 0.f, tot2 = 0.f;
    #pragma unroll
    for (int i = 0; i < 8; i++) { tot += rs[i]; tot2 += rss[i]; }

    float mu  = tot * (1.0f / D_MODEL);
    float var = tot2 * (1.0f / D_MODEL) - mu * mu;
    float r   = rsqrtf(var + 1e-5f);

    float4 gv = *(const float4*)&g[t * 4];
    float4 bv = *(const float4*)&b[t * 4];
    __half2 h0 = __floats2half2_rn((v.x - mu) * r * gv.x + bv.x,
                                   (v.y - mu) * r * gv.y + bv.y);
    __half2 h1 = __floats2half2_rn((v.z - mu) * r * gv.z + bv.z,
                                   (v.w - mu) * r * gv.w + bv.w);
    uint2 o; o.x = *(unsigned*)&h0; o.y = *(unsigned*)&h1;
    *(uint2*)&yr[t * 4] = o;
}

// ---------------- GELU (tanh approximation) --------------------------------
__device__ __forceinline__ float gelu_f(float x) {
    float x3 = x * x * x;
    float t  = tanhf(0.7978845608028654f * (x + 0.044715f * x3));
    return 0.5f * x * (1.0f + t);
}

__device__ __forceinline__ unsigned smem_u32(const void* p) {
    return (unsigned)__cvta_generic_to_shared(p);
}

__device__ __forceinline__ void mma_16816(float* c, const unsigned* a,
                                          unsigned b0, unsigned b1) {
    asm volatile(
        "mma.sync.aligned.m16n8k16.row.col.f32.f16.f16.f32 "
        "{%0,%1,%2,%3}, {%4,%5,%6,%7}, {%8,%9}, {%0,%1,%2,%3};"
        : "+f"(c[0]), "+f"(c[1]), "+f"(c[2]), "+f"(c[3])
        : "r"(a[0]), "r"(a[1]), "r"(a[2]), "r"(a[3]), "r"(b0), "r"(b1));
}

// ---------------- HGEMM: 3-stage cp.async pipeline --------------------------
#define HBK  32
#define ASTR 40
#define BSTR 136
#define HG_STAGES 3
#define HG_SMEM (HG_STAGES * (128 * ASTR + HBK * BSTR) * 2)

__global__ __launch_bounds__(256, 2)
void hgemm_kernel(const __half* __restrict__ A, const __half* __restrict__ W,
                  const float* __restrict__ bias, const float* __restrict__ residual,
                  void* __restrict__ Cout, int M, int N, int K, int ldc,
                  int do_gelu, int out_half) {
    extern __shared__ __half hsm[];
    __half* As = hsm;                               // [3][128*ASTR]
    __half* Bs = hsm + HG_STAGES * 128 * ASTR;      // [3][HBK*BSTR]

    const int tid  = threadIdx.x;
    const int wid  = tid >> 5, lane = tid & 31;
    const int wm   = (wid & 3) << 5;
    const int wn   = (wid >> 2) << 6;
    const int row0 = blockIdx.y << 7;
    const int col0 = blockIdx.x << 7;

    const int ar0 = tid >> 2,         ac0 = (tid & 3) << 3;
    const int ar1 = (tid + 256) >> 2, ac1 = ((tid + 256) & 3) << 3;
    const int br0 = tid >> 4,         bc0 = (tid & 15) << 3;
    const int br1 = (tid + 256) >> 4, bc1 = ((tid + 256) & 15) << 3;

    float acc[2][8][4];
    #pragma unroll
    for (int i = 0; i < 2; i++)
        #pragma unroll
        for (int j = 0; j < 8; j++)
            #pragma unroll
            for (int x = 0; x < 4; x++) acc[i][j][x] = 0.f;

    const int KT = K / HBK;

    #define LOAD_TILES(kt, st) do {                                                \
        int k0 = (kt) * HBK;                                                       \
        __half* ab = As + (st) * 128 * ASTR;                                       \
        __half* bb = Bs + (st) * HBK * BSTR;                                       \
        unsigned d0 = smem_u32(ab + ar0 * ASTR + ac0);                             \
        asm volatile("cp.async.cg.shared.global [%0], [%1], 16;" ::                \
            "r"(d0), "l"(&A[(size_t)(row0 + ar0) * K + k0 + ac0]));                \
        unsigned d1 = smem_u32(ab + ar1 * ASTR + ac1);                             \
        asm volatile("cp.async.cg.shared.global [%0], [%1], 16;" ::                \
            "r"(d1), "l"(&A[(size_t)(row0 + ar1) * K + k0 + ac1]));                \
        unsigned d2 = smem_u32(bb + br0 * BSTR + bc0);                             \
        asm volatile("cp.async.cg.shared.global [%0], [%1], 16;" ::                \
            "r"(d2), "l"(&W[(size_t)(k0 + br0) * N + col0 + bc0]));                \
        unsigned d3 = smem_u32(bb + br1 * BSTR + bc1);                             \
        asm volatile("cp.async.cg.shared.global [%0], [%1], 16;" ::                \
            "r"(d3), "l"(&W[(size_t)(k0 + br1) * N + col0 + bc1]));                \
    } while (0)

    LOAD_TILES(0, 0);
    asm volatile("cp.async.commit_group;");
    LOAD_TILES(1, 1);
    asm volatile("cp.async.commit_group;");

    for (int kt = 0; kt < KT; kt++) {
        const int st = kt % HG_STAGES;
        asm volatile("cp.async.wait_group 1;");
        __syncthreads();
        if (kt + 2 < KT) LOAD_TILES(kt + 2, (kt + 2) % HG_STAGES);
        asm volatile("cp.async.commit_group;");

        __half* ab = As + st * 128 * ASTR;
        __half* bb = Bs + st * HBK * BSTR;

        #pragma unroll
        for (int ks = 0; ks < 2; ks++) {
            const int kk = ks << 4;
            unsigned a[2][4];
            #pragma unroll
            for (int mt = 0; mt < 2; mt++) {
                int r = wm + (mt << 4) + (lane & 15);
                int c = kk + ((lane >> 4) << 3);
                unsigned addr = smem_u32(ab + r * ASTR + c);
                asm volatile("ldmatrix.sync.aligned.m8n8.x4.shared.b16 {%0,%1,%2,%3}, [%4];"
                    : "=r"(a[mt][0]), "=r"(a[mt][1]), "=r"(a[mt][2]), "=r"(a[mt][3])
                    : "r"(addr));
            }
            unsigned bf[4][4];
            #pragma unroll
            for (int nq = 0; nq < 4; nq++) {
                int r = kk + (lane & 15);
                int c = wn + (nq << 4) + ((lane >> 4) << 3);
                unsigned addr = smem_u32(bb + r * BSTR + c);
                asm volatile("ldmatrix.sync.aligned.m8n8.x4.trans.shared.b16 {%0,%1,%2,%3}, [%4];"
                    : "=r"(bf[nq][0]), "=r"(bf[nq][1]), "=r"(bf[nq][2]), "=r"(bf[nq][3])
                    : "r"(addr));
            }
            #pragma unroll
            for (int mt = 0; mt < 2; mt++)
                #pragma unroll
                for (int nt = 0; nt < 8; nt++)
                    mma_16816(acc[mt][nt], a[mt],
                              bf[nt >> 1][(nt & 1) * 2], bf[nt >> 1][(nt & 1) * 2 + 1]);
        }
    }

    const int lr = lane >> 2;
    const int lc = (lane & 3) << 1;
    #pragma unroll
    for (int mt = 0; mt < 2; mt++) {
        #pragma unroll
        for (int h2 = 0; h2 < 2; h2++) {
            int gr = row0 + wm + (mt << 4) + lr + (h2 << 3);
            #pragma unroll
            for (int nt = 0; nt < 8; nt++) {
                int gc = col0 + wn + (nt << 3) + lc;
                float v0 = acc[mt][nt][h2 * 2 + 0] + bias[gc];
                float v1 = acc[mt][nt][h2 * 2 + 1] + bias[gc + 1];
                if (residual) {
                    float2 rv = *(const float2*)&residual[(size_t)gr * ldc + gc];
                    v0 += rv.x; v1 += rv.y;
                }
                if (do_gelu) { v0 = gelu_f(v0); v1 = gelu_f(v1); }
                if (out_half) {
                    __half2 hv = __floats2half2_rn(v0, v1);
                    *(__half2*)((__half*)Cout + (size_t)gr * ldc + gc) = hv;
                } else {
                    float2 ov; ov.x = v0; ov.y = v1;
                    *(float2*)((float*)Cout + (size_t)gr * ldc + gc) = ov;
                }
            }
        }
    }
}

// ---------------- tensor-core flash attention (cp.async double buffer) ------
#define QSTR 72
#define QS_ELEMS (64 * QSTR)
// dyn smem: Qs | Ks[2] | Vs[2] | Ms[2]
#define ATTN_SMEM (QS_ELEMS * 5 * 2 + 2 * 64 * 64)

__global__ __launch_bounds__(128)
void attn_mma_kernel(const __half* __restrict__ Q, const __half* __restrict__ K,
                     const __half* __restrict__ V,
                     const unsigned char* __restrict__ mask,
                     __half* __restrict__ O, int Lq, int Lk,
                     int ldq, int ldkv, int causal) {
    extern __shared__ __half asm_sm[];
    __half* Qs = asm_sm;                       // [64][QSTR]
    __half* Ks = asm_sm + QS_ELEMS;            // [2][64][QSTR]
    __half* Vs = asm_sm + 3 * QS_ELEMS;        // [2][64][QSTR]
    unsigned char* Ms = (unsigned char*)(asm_sm + 5 * QS_ELEMS);  // [2][64][64]

    const int qt = blockIdx.x, h = blockIdx.y, b = blockIdx.z;
    const int tid = threadIdx.x, w = tid >> 5, lane = tid & 31;
    const int q0 = qt * 64;
    const int lr = lane >> 2;
    const int qq = (lane & 3) << 1;

    const __half* Qb = Q + ((size_t)(b * Lq + q0)) * ldq + h * DK_;
    const __half* Kb = K + ((size_t)b * Lk) * ldkv + h * DK_;
    const __half* Vb = V + ((size_t)b * Lk) * ldkv + h * DK_;

    // ---- load Q tile, scaled by 1/8 (exact in fp16) ----
    const __half2 qscale = __float2half2_rn(0.125f);
    #pragma unroll
    for (int p = 0; p < 4; p++) {
        int idx = p * 128 + tid;
        int r = idx >> 3, c8 = (idx & 7) << 3;
        uint4 d = *(const uint4*)&Qb[(size_t)r * ldq + c8];
        __half2* hp = (__half2*)&d;
        #pragma unroll
        for (int j = 0; j < 4; j++) hp[j] = __hmul2(hp[j], qscale);
        *(uint4*)&Qs[r * QSTR + c8] = d;
    }

    #define LOAD_KV(kt, buf) do {                                                  \
        int kg_ = (kt) * 64;                                                       \
        __half* kb_ = Ks + (buf) * QS_ELEMS;                                       \
        __half* vb_ = Vs + (buf) * QS_ELEMS;                                       \
        _Pragma("unroll")                                                          \
        for (int p = 0; p < 4; p++) {                                              \
            int idx = p * 128 + tid;                                               \
            int r = idx >> 3, c8 = (idx & 7) << 3;                                 \
            unsigned dk = smem_u32(kb_ + r * QSTR + c8);                           \
            asm volatile("cp.async.cg.shared.global [%0], [%1], 16;" ::            \
                "r"(dk), "l"(&Kb[(size_t)(kg_ + r) * ldkv + c8]));                 \
            unsigned dv = smem_u32(vb_ + r * QSTR + c8);                           \
            asm volatile("cp.async.cg.shared.global [%0], [%1], 16;" ::            \
                "r"(dv), "l"(&Vb[(size_t)(kg_ + r) * ldkv + c8]));                 \
        }                                                                          \
        if (mask) {                                                                \
            unsigned char* mb_ = Ms + (buf) * 4096;                                \
            _Pragma("unroll")                                                      \
            for (int p = 0; p < 2; p++) {                                          \
                int idx = p * 128 + tid;                                           \
                int r = idx >> 2, c16 = (idx & 3) << 4;                            \
                unsigned dm = smem_u32(mb_ + r * 64 + c16);                        \
                asm volatile("cp.async.cg.shared.global [%0], [%1], 16;" ::        \
                    "r"(dm), "l"(mask + ((size_t)(b * Lq + q0 + r)) * Lk + kg_ + c16)); \
            }                                                                      \
        }                                                                          \
        asm volatile("cp.async.commit_group;");                                    \
    } while (0)

    LOAD_KV(0, 0);
    __syncthreads();   // Qs visible

    // ---- hoist Q fragments ----
    unsigned qf[4][4];
    #pragma unroll
    for (int kc = 0; kc < 4; kc++) {
        int r = w * 16 + (lane & 15);
        int c = kc * 16 + ((lane >> 4) << 3);
        unsigned addr = smem_u32(Qs + r * QSTR + c);
        asm volatile("ldmatrix.sync.aligned.m8n8.x4.shared.b16 {%0,%1,%2,%3}, [%4];"
            : "=r"(qf[kc][0]), "=r"(qf[kc][1]), "=r"(qf[kc][2]), "=r"(qf[kc][3])
            : "r"(addr));
    }

    float o[8][4];
    #pragma unroll
    for (int i = 0; i < 8; i++)
        #pragma unroll
        for (int j = 0; j < 4; j++) o[i][j] = 0.f;
    float mrow[2] = {-1e30f, -1e30f}, lrow[2] = {0.f, 0.f};

    const int ntile = causal ? (qt + 1) : (Lk / 64);

    for (int kt = 0; kt < ntile; kt++) {
        const int buf = kt & 1;
        asm volatile("cp.async.wait_group 0;");
        __syncthreads();   // tile kt ready; all warps done with buf^1
        if (kt + 1 < ntile) LOAD_KV(kt + 1, buf ^ 1);

        __half* kb = Ks + buf * QS_ELEMS;
        __half* vb = Vs + buf * QS_ELEMS;
        unsigned char* mb2 = Ms + buf * 4096;

        // ---- S = Q K^T ----
        float s[8][4];
        #pragma unroll
        for (int i = 0; i < 8; i++)
            #pragma unroll
            for (int j = 0; j < 4; j++) s[i][j] = 0.f;

        #pragma unroll
        for (int kc = 0; kc < 4; kc++) {
            #pragma unroll
            for (int np = 0; np < 4; np++) {
                unsigned kf[4];
                int r = np * 16 + (lane & 15);
                int c = kc * 16 + ((lane >> 4) << 3);
                unsigned addr = smem_u32(kb + r * QSTR + c);
                asm volatile("ldmatrix.sync.aligned.m8n8.x4.shared.b16 {%0,%1,%2,%3}, [%4];"
                    : "=r"(kf[0]), "=r"(kf[1]), "=r"(kf[2]), "=r"(kf[3])
                    : "r"(addr));
                mma_16816(s[2 * np],     qf[kc], kf[0], kf[2]);
                mma_16816(s[2 * np + 1], qf[kc], kf[1], kf[3]);
            }
        }

        // ---- masking ----
        if (mask) {
            int r0 = w * 16 + lr, r1 = r0 + 8;
            #pragma unroll
            for (int nt = 0; nt < 8; nt++) {
                int c0 = nt * 8 + qq;
                if (mb2[r0 * 64 + c0])     s[nt][0] = -3.0e38f;
                if (mb2[r0 * 64 + c0 + 1]) s[nt][1] = -3.0e38f;
                if (mb2[r1 * 64 + c0])     s[nt][2] = -3.0e38f;
                if (mb2[r1 * 64 + c0 + 1]) s[nt][3] = -3.0e38f;
            }
        }
        if (causal && kt == qt) {
            int r0 = w * 16 + lr, r1 = r0 + 8;
            #pragma unroll
            for (int nt = 0; nt < 8; nt++) {
                int c0 = nt * 8 + qq;
                if (c0 > r0)     s[nt][0] = -3.0e38f;
                if (c0 + 1 > r0) s[nt][1] = -3.0e38f;
                if (c0 > r1)     s[nt][2] = -3.0e38f;
                if (c0 + 1 > r1) s[nt][3] = -3.0e38f;
            }
        }

        // ---- online softmax ----
        #pragma unroll
        for (int r = 0; r < 2; r++) {
            float mx = -3.0e38f;
            #pragma unroll
            for (int nt = 0; nt < 8; nt++)
                mx = fmaxf(mx, fmaxf(s[nt][2 * r], s[nt][2 * r + 1]));
            mx = fmaxf(mx, __shfl_xor_sync(0xffffffffu, mx, 1));
            mx = fmaxf(mx, __shfl_xor_sync(0xffffffffu, mx, 2));
            float mn   = fmaxf(mrow[r], mx);
            float corr = __expf(mrow[r] - mn);
            mrow[r] = mn;
            float ls = 0.f;
            #pragma unroll
            for (int nt = 0; nt < 8; nt++) {
                s[nt][2 * r]     = __expf(s[nt][2 * r]     - mn);
                s[nt][2 * r + 1] = __expf(s[nt][2 * r + 1] - mn);
                ls += s[nt][2 * r] + s[nt][2 * r + 1];
            }
            ls += __shfl_xor_sync(0xffffffffu, ls, 1);
            ls += __shfl_xor_sync(0xffffffffu, ls, 2);
            lrow[r] = lrow[r] * corr + ls;
            #pragma unroll
            for (int nt = 0; nt < 8; nt++) {
                o[nt][2 * r]     *= corr;
                o[nt][2 * r + 1] *= corr;
            }
        }

        // ---- O += P V ----
        #pragma unroll
        for (int kc = 0; kc < 4; kc++) {
            unsigned pa[4];
            __half2 t0 = __floats2half2_rn(s[2 * kc][0],     s[2 * kc][1]);
            __half2 t1 = __floats2half2_rn(s[2 * kc][2],     s[2 * kc][3]);
            __half2 t2 = __floats2half2_rn(s[2 * kc + 1][0], s[2 * kc + 1][1]);
            __half2 t3 = __floats2half2_rn(s[2 * kc + 1][2], s[2 * kc + 1][3]);
            pa[0] = *(unsigned*)&t0; pa[1] = *(unsigned*)&t1;
            pa[2] = *(unsigned*)&t2; pa[3] = *(unsigned*)&t3;
            #pragma unroll
            for (int nd = 0; nd < 4; nd++) {
                unsigned vf[4];
                int r = kc * 16 + (lane & 15);
                int c = nd * 16 + ((lane >> 4) << 3);
                unsigned addr = smem_u32(vb + r * QSTR + c);
                asm volatile("ldmatrix.sync.aligned.m8n8.x4.trans.shared.b16 {%0,%1,%2,%3}, [%4];"
                    : "=r"(vf[0]), "=r"(vf[1]), "=r"(vf[2]), "=r"(vf[3])
                    : "r"(addr));
                mma_16816(o[2 * nd],     pa, vf[0], vf[1]);
                mma_16816(o[2 * nd + 1], pa, vf[2], vf[3]);
            }
        }
    }

    // ---- epilogue ----
    #pragma unroll
    for (int r = 0; r < 2; r++) {
        float inv = 1.0f / lrow[r];
        int row = q0 + w * 16 + lr + r * 8;
        __half* op = O + (size_t)(b * Lq + row) * D_MODEL + h * DK_;
        #pragma unroll
        for (int nt = 0; nt < 8; nt++) {
            int col = nt * 8 + qq;
            __half2 hv = __floats2half2_rn(o[nt][2 * r] * inv, o[nt][2 * r + 1] * inv);
            *(__half2*)&op[col] = hv;
        }
    }
}

// ---------------- launch ---------------------------------------------------
extern "C" void kernel_launch(void* const* d_in, const int* in_sizes, int n_in,
                              void* d_out, int out_size) {
    const float* tgt      = (const float*)d_in[0];
    const float* memory   = (const float*)d_in[1];
    const unsigned char* src_pad = (const unsigned char*)d_in[2];
    // d_in[3] = tgt_mask (causal triu) — handled via causal flag
    const float* self_wq  = (const float*)d_in[4];
    const float* self_bq  = (const float*)d_in[5];
    const float* self_wk  = (const float*)d_in[6];
    const float* self_bk  = (const float*)d_in[7];
    const float* self_wv  = (const float*)d_in[8];
    const float* self_bv  = (const float*)d_in[9];
    const float* self_wo  = (const float*)d_in[10];
    const float* self_bo  = (const float*)d_in[11];
    const float* cross_wq = (const float*)d_in[12];
    const float* cross_bq = (const float*)d_in[13];
    const float* cross_wk = (const float*)d_in[14];
    const float* cross_bk = (const float*)d_in[15];
    const float* cross_wv = (const float*)d_in[16];
    const float* cross_bv = (const float*)d_in[17];
    const float* cross_wo = (const float*)d_in[18];
    const float* cross_bo = (const float*)d_in[19];
    const float* ln1_g    = (const float*)d_in[20];
    const float* ln1_b    = (const float*)d_in[21];
    const float* ln2_g    = (const float*)d_in[22];
    const float* ln2_b    = (const float*)d_in[23];
    const float* ln3_g    = (const float*)d_in[24];
    const float* ln3_b    = (const float*)d_in[25];
    const float* ffn_w1   = (const float*)d_in[26];
    const float* ffn_b1   = (const float*)d_in[27];
    const float* ffn_w2   = (const float*)d_in[28];
    const float* ffn_b2   = (const float*)d_in[29];

    float *x1, *x2, *bias3, *bias2;
    __half *qkv16, *q16, *kv16, *ln16, *ctx16, *mem16, *ffn16, *w16;
    cudaGetSymbolAddress((void**)&x1,    g_x1);
    cudaGetSymbolAddress((void**)&x2,    g_x2);
    cudaGetSymbolAddress((void**)&qkv16, g_qkv16);
    cudaGetSymbolAddress((void**)&q16,   g_q16);
    cudaGetSymbolAddress((void**)&kv16,  g_kv16);
    cudaGetSymbolAddress((void**)&ln16,  g_ln16);
    cudaGetSymbolAddress((void**)&ctx16, g_ctx16);
    cudaGetSymbolAddress((void**)&mem16, g_mem16);
    cudaGetSymbolAddress((void**)&ffn16, g_ffn16);
    cudaGetSymbolAddress((void**)&w16,   g_w16);
    cudaGetSymbolAddress((void**)&bias3, g_bias3);
    cudaGetSymbolAddress((void**)&bias2, g_bias2);

    const int MM = D_MODEL * D_MODEL;   // 1M elements
    __half* W3    = w16;                        // [1024][3072]
    __half* swo16 = w16 + 3 * MM;
    __half* cwq16 = w16 + 4 * MM;
    __half* Wkv   = w16 + 5 * MM;               // [1024][2048]
    __half* cwo16 = w16 + 7 * MM;
    __half* w1_16 = w16 + 8 * MM;               // [1024][4096]
    __half* w2_16 = w16 + 12 * MM;              // [4096][1024]

    float* out = (float*)d_out;

    cudaFuncSetAttribute(hgemm_kernel,
                         cudaFuncAttributeMaxDynamicSharedMemorySize, HG_SMEM);
    cudaFuncSetAttribute(attn_mma_kernel,
                         cudaFuncAttributeMaxDynamicSharedMemorySize, ATTN_SMEM);

    // ---- batched conversions ----
    ConvArgs ca;
    auto setj = [&](int i, const float* s, __half* d, int nc, int ds, long long n) {
        ca.jobs[i] = { s, d, nc, ds };
        ca.prefix[i + 1] = ca.prefix[i] + n;
    };
    ca.prefix[0] = 0;
    setj(0,  self_wq,  W3,                 D_MODEL, 3 * D_MODEL, MM);
    setj(1,  self_wk,  W3 + D_MODEL,       D_MODEL, 3 * D_MODEL, MM);
    setj(2,  self_wv,  W3 + 2 * D_MODEL,   D_MODEL, 3 * D_MODEL, MM);
    setj(3,  self_wo,  swo16,              D_MODEL, D_MODEL,     MM);
    setj(4,  cross_wq, cwq16,              D_MODEL, D_MODEL,     MM);
    setj(5,  cross_wk, Wkv,                D_MODEL, 2 * D_MODEL, MM);
    setj(6,  cross_wv, Wkv + D_MODEL,      D_MODEL, 2 * D_MODEL, MM);
    setj(7,  cross_wo, cwo16,              D_MODEL, D_MODEL,     MM);
    setj(8,  ffn_w1,   w1_16,              DFF_,    DFF_,        (long long)D_MODEL * DFF_);
    setj(9,  ffn_w2,   w2_16,              D_MODEL, D_MODEL,     (long long)D_MODEL * DFF_);
    setj(10, memory,   mem16,              D_MODEL, D_MODEL,     (long long)NTOK * D_MODEL);
    long long total8 = ca.prefix[11] / 8;
    convmany_kernel<<<(unsigned)((total8 + 255) / 256), 256>>>(ca);
    bias_concat_kernel<<<4, 256>>>(self_bq, self_bk, self_bv, bias3,
                                   cross_bk, cross_bv, bias2);

    dim3 gQKV(3 * D_MODEL / 128, NTOK / 128);   // (24, 32)
    dim3 gKV (2 * D_MODEL / 128, NTOK / 128);   // (16, 32)
    dim3 gD  (D_MODEL / 128,     NTOK / 128);   // (8, 32)
    dim3 gF  (DFF_ / 128,        NTOK / 128);   // (32, 32)
    dim3 gA  (LT_ / 64, NH, B_);

    // ---- sublayer 1: self-attention (pre-norm) ----
    ln_kernel<<<NTOK, 256>>>(tgt, ln1_g, ln1_b, ln16);
    hgemm_kernel<<<gQKV, 256, HG_SMEM>>>(ln16, W3, bias3, nullptr, qkv16,
                                         NTOK, 3 * D_MODEL, D_MODEL, 3 * D_MODEL, 0, 1);
    attn_mma_kernel<<<gA, 128, ATTN_SMEM>>>(qkv16, qkv16 + D_MODEL, qkv16 + 2 * D_MODEL,
                                            nullptr, ctx16, LT_, LT_,
                                            3 * D_MODEL, 3 * D_MODEL, 1);
    hgemm_kernel<<<gD, 256, HG_SMEM>>>(ctx16, swo16, self_bo, tgt, x1,
                                       NTOK, D_MODEL, D_MODEL, D_MODEL, 0, 0);

    // ---- sublayer 2: cross-attention (pre-norm; K/V from raw memory) ----
    ln_kernel<<<NTOK, 256>>>(x1, ln2_g, ln2_b, ln16);
    hgemm_kernel<<<gD, 256, HG_SMEM>>>(ln16, cwq16, cross_bq, nullptr, q16,
                                       NTOK, D_MODEL, D_MODEL, D_MODEL, 0, 1);
    hgemm_kernel<<<gKV, 256, HG_SMEM>>>(mem16, Wkv, bias2, nullptr, kv16,
                                        NTOK, 2 * D_MODEL, D_MODEL, 2 * D_MODEL, 0, 1);
    attn_mma_kernel<<<gA, 128, ATTN_SMEM>>>(q16, kv16, kv16 + D_MODEL,
                                            src_pad, ctx16, LT_, LS_,
                                            D_MODEL, 2 * D_MODEL, 0);
    hgemm_kernel<<<gD, 256, HG_SMEM>>>(ctx16, cwo16, cross_bo, x1, x2,
                                       NTOK, D_MODEL, D_MODEL, D_MODEL, 0, 0);

    // ---- sublayer 3: FFN (pre-norm) ----
    ln_kernel<<<NTOK, 256>>>(x2, ln3_g, ln3_b, ln16);
    hgemm_kernel<<<gF, 256, HG_SMEM>>>(ln16, w1_16, ffn_b1, nullptr, ffn16,
                                       NTOK, DFF_, D_MODEL, DFF_, 1, 1);
    hgemm_kernel<<<gD, 256, HG_SMEM>>>(ffn16, w2_16, ffn_b2, x2, out,
                                       NTOK, D_MODEL, DFF_, D_MODEL, 0, 0);
}

// round 8
// speedup vs baseline: 17.1195x; 1.0282x over previous
#include <cuda_runtime.h>
#include <cuda_fp16.h>
#include <math.h>

// ---------------- problem constants ----------------
#define D_MODEL 1024
#define NH      16
#define DK_     64
#define DFF_    4096
#define B_      4
#define LT_     1024
#define LS_     1024
#define NTOK    (B_ * LT_)   // 4096 rows

// ---------------- scratch (static device globals; no allocs allowed) -------
__device__ float  g_x1 [NTOK * D_MODEL];
__device__ float  g_x2 [NTOK * D_MODEL];
__device__ __half g_qkv16[NTOK * 3 * D_MODEL];   // self q|k|v fused (ld 3072)
__device__ __half g_q16  [NTOK * D_MODEL];       // cross q
__device__ __half g_kv16 [NTOK * 2 * D_MODEL];   // cross k|v fused (ld 2048)
__device__ __half g_ln16 [NTOK * D_MODEL];
__device__ __half g_ctx16[NTOK * D_MODEL];
__device__ __half g_mem16[NTOK * D_MODEL];
__device__ __half g_ffn16[NTOK * DFF_];
// weight pool: W3(3M) | swo(1M) | cwq(1M) | Wkv(2M) | cwo(1M) | w1(4M) | w2(4M)
__device__ __half g_w16[16 * 1024 * 1024];
__device__ float  g_bias3[3 * D_MODEL];
__device__ float  g_bias2[2 * D_MODEL];

// ---------------- batched fp32 -> fp16 convert (strided dst) ---------------
struct Job { const float* src; __half* dst; int ncols; int dstride; };
struct ConvArgs { Job jobs[8]; long long prefix[9]; int njobs; };

__global__ void convmany_kernel(ConvArgs a) {
    long long g = ((long long)blockIdx.x * blockDim.x + threadIdx.x) * 8;
    if (g >= a.prefix[a.njobs]) return;
    int seg = 0;
    while (g >= a.prefix[seg + 1]) seg++;
    long long off = g - a.prefix[seg];
    Job j = a.jobs[seg];
    int row = (int)(off / j.ncols);
    int col = (int)(off - (long long)row * j.ncols);
    const float* s = j.src + off;
    __half* d = j.dst + (size_t)row * j.dstride + col;
    float4 x0 = *(const float4*)s;
    float4 x1 = *(const float4*)(s + 4);
    __half2 h0 = __floats2half2_rn(x0.x, x0.y), h1 = __floats2half2_rn(x0.z, x0.w);
    __half2 h2 = __floats2half2_rn(x1.x, x1.y), h3 = __floats2half2_rn(x1.z, x1.w);
    uint4 o;
    o.x = *(unsigned*)&h0; o.y = *(unsigned*)&h1;
    o.z = *(unsigned*)&h2; o.w = *(unsigned*)&h3;
    *(uint4*)d = o;
}

__global__ void bias_concat_kernel(const float* b0, const float* b1, const float* b2,
                                   float* d3, const float* c0, const float* c1, float* d2) {
    int t = blockIdx.x * blockDim.x + threadIdx.x;
    if (t < D_MODEL) {
        d3[t] = b0[t]; d3[D_MODEL + t] = b1[t]; d3[2 * D_MODEL + t] = b2[t];
        d2[t] = c0[t]; d2[D_MODEL + t] = c1[t];
    }
}

// ---------------- LayerNorm: fp32 in, fp16 out -----------------------------
__global__ void ln_kernel(const float* __restrict__ x, const float* __restrict__ g,
                          const float* __restrict__ b, __half* __restrict__ y) {
    int row = blockIdx.x;
    const float* xr = x + (size_t)row * D_MODEL;
    __half*      yr = y + (size_t)row * D_MODEL;
    int t = threadIdx.x;

    float4 v = *(const float4*)&xr[t * 4];
    float s  = v.x + v.y + v.z + v.w;
    float ss = v.x * v.x + v.y * v.y + v.z * v.z + v.w * v.w;

    #pragma unroll
    for (int o = 16; o; o >>= 1) {
        s  += __shfl_xor_sync(0xffffffffu, s,  o);
        ss += __shfl_xor_sync(0xffffffffu, ss, o);
    }
    __shared__ float rs[8], rss[8];
    int w = t >> 5, lane = t & 31;
    if (lane == 0) { rs[w] = s; rss[w] = ss; }
    __syncthreads();
    float tot = 0.f, tot2 = 0.f;
    #pragma unroll
    for (int i = 0; i < 8; i++) { tot += rs[i]; tot2 += rss[i]; }

    float mu  = tot * (1.0f / D_MODEL);
    float var = tot2 * (1.0f / D_MODEL) - mu * mu;
    float r   = rsqrtf(var + 1e-5f);

    float4 gv = *(const float4*)&g[t * 4];
    float4 bv = *(const float4*)&b[t * 4];
    __half2 h0 = __floats2half2_rn((v.x - mu) * r * gv.x + bv.x,
                                   (v.y - mu) * r * gv.y + bv.y);
    __half2 h1 = __floats2half2_rn((v.z - mu) * r * gv.z + bv.z,
                                   (v.w - mu) * r * gv.w + bv.w);
    uint2 o; o.x = *(unsigned*)&h0; o.y = *(unsigned*)&h1;
    *(uint2*)&yr[t * 4] = o;
}

// ---------------- GELU (tanh approximation) --------------------------------
__device__ __forceinline__ float gelu_f(float x) {
    float x3 = x * x * x;
    float t  = tanhf(0.7978845608028654f * (x + 0.044715f * x3));
    return 0.5f * x * (1.0f + t);
}

__device__ __forceinline__ unsigned smem_u32(const void* p) {
    return (unsigned)__cvta_generic_to_shared(p);
}

__device__ __forceinline__ void mma_16816(float* c, const unsigned* a,
                                          unsigned b0, unsigned b1) {
    asm volatile(
        "mma.sync.aligned.m16n8k16.row.col.f32.f16.f16.f32 "
        "{%0,%1,%2,%3}, {%4,%5,%6,%7}, {%8,%9}, {%0,%1,%2,%3};"
        : "+f"(c[0]), "+f"(c[1]), "+f"(c[2]), "+f"(c[3])
        : "r"(a[0]), "r"(a[1]), "r"(a[2]), "r"(a[3]), "r"(b0), "r"(b1));
}

// ---------------- HGEMM: BK=64, 3-stage cp.async pipeline -------------------
#define HBK  64
#define ASTR 72     // 64 + 8 halfs pad
#define BSTR 136    // 128 + 8 halfs pad
#define HG_STAGES 3
#define HG_SMEM (HG_STAGES * (128 * ASTR + HBK * BSTR) * 2)

__global__ __launch_bounds__(256, 2)
void hgemm_kernel(const __half* __restrict__ A, const __half* __restrict__ W,
                  const float* __restrict__ bias, const float* __restrict__ residual,
                  void* __restrict__ Cout, int M, int N, int K, int ldc,
                  int do_gelu, int out_half) {
    extern __shared__ __half hsm[];
    __half* As = hsm;                               // [3][128*ASTR]
    __half* Bs = hsm + HG_STAGES * 128 * ASTR;      // [3][HBK*BSTR]

    const int tid  = threadIdx.x;
    const int wid  = tid >> 5, lane = tid & 31;
    const int wm   = (wid & 3) << 5;
    const int wn   = (wid >> 2) << 6;
    const int row0 = blockIdx.y << 7;
    const int col0 = blockIdx.x << 7;

    // A tile: 128 rows x 64 halfs = 1024 chunks of 16B; 4 per thread
    // B tile: 64 rows x 128 halfs = 1024 chunks of 16B; 4 per thread
    float acc[2][8][4];
    #pragma unroll
    for (int i = 0; i < 2; i++)
        #pragma unroll
        for (int j = 0; j < 8; j++)
            #pragma unroll
            for (int x = 0; x < 4; x++) acc[i][j][x] = 0.f;

    const int KT = K / HBK;

    #define LOAD_TILES(kt, st) do {                                                \
        int k0 = (kt) * HBK;                                                       \
        __half* ab = As + (st) * 128 * ASTR;                                       \
        __half* bb = Bs + (st) * HBK * BSTR;                                       \
        _Pragma("unroll")                                                          \
        for (int p = 0; p < 4; p++) {                                              \
            int id = p * 256 + tid;                                                \
            int ar = id >> 3, ac = (id & 7) << 3;                                  \
            unsigned da = smem_u32(ab + ar * ASTR + ac);                           \
            asm volatile("cp.async.cg.shared.global [%0], [%1], 16;" ::            \
                "r"(da), "l"(&A[(size_t)(row0 + ar) * K + k0 + ac]));              \
            int br = id >> 4, bc = (id & 15) << 3;                                 \
            unsigned db = smem_u32(bb + br * BSTR + bc);                           \
            asm volatile("cp.async.cg.shared.global [%0], [%1], 16;" ::            \
                "r"(db), "l"(&W[(size_t)(k0 + br) * N + col0 + bc]));              \
        }                                                                          \
        asm volatile("cp.async.commit_group;");                                    \
    } while (0)

    LOAD_TILES(0, 0);
    LOAD_TILES(1, 1);

    for (int kt = 0; kt < KT; kt++) {
        const int st = kt % HG_STAGES;
        if (kt + 1 < KT) asm volatile("cp.async.wait_group 1;");
        else             asm volatile("cp.async.wait_group 0;");
        __syncthreads();
        if (kt + 2 < KT) LOAD_TILES(kt + 2, (kt + 2) % HG_STAGES);
        else             asm volatile("cp.async.commit_group;");

        __half* ab = As + st * 128 * ASTR;
        __half* bb = Bs + st * HBK * BSTR;

        #pragma unroll
        for (int ks = 0; ks < 4; ks++) {
            const int kk = ks << 4;
            unsigned a[2][4];
            #pragma unroll
            for (int mt = 0; mt < 2; mt++) {
                int r = wm + (mt << 4) + (lane & 15);
                int c = kk + ((lane >> 4) << 3);
                unsigned addr = smem_u32(ab + r * ASTR + c);
                asm volatile("ldmatrix.sync.aligned.m8n8.x4.shared.b16 {%0,%1,%2,%3}, [%4];"
                    : "=r"(a[mt][0]), "=r"(a[mt][1]), "=r"(a[mt][2]), "=r"(a[mt][3])
                    : "r"(addr));
            }
            unsigned bf[4][4];
            #pragma unroll
            for (int nq = 0; nq < 4; nq++) {
                int r = kk + (lane & 15);
                int c = wn + (nq << 4) + ((lane >> 4) << 3);
                unsigned addr = smem_u32(bb + r * BSTR + c);
                asm volatile("ldmatrix.sync.aligned.m8n8.x4.trans.shared.b16 {%0,%1,%2,%3}, [%4];"
                    : "=r"(bf[nq][0]), "=r"(bf[nq][1]), "=r"(bf[nq][2]), "=r"(bf[nq][3])
                    : "r"(addr));
            }
            #pragma unroll
            for (int mt = 0; mt < 2; mt++)
                #pragma unroll
                for (int nt = 0; nt < 8; nt++)
                    mma_16816(acc[mt][nt], a[mt],
                              bf[nt >> 1][(nt & 1) * 2], bf[nt >> 1][(nt & 1) * 2 + 1]);
        }
    }

    const int lr = lane >> 2;
    const int lc = (lane & 3) << 1;
    #pragma unroll
    for (int mt = 0; mt < 2; mt++) {
        #pragma unroll
        for (int h2 = 0; h2 < 2; h2++) {
            int gr = row0 + wm + (mt << 4) + lr + (h2 << 3);
            #pragma unroll
            for (int nt = 0; nt < 8; nt++) {
                int gc = col0 + wn + (nt << 3) + lc;
                float v0 = acc[mt][nt][h2 * 2 + 0] + bias[gc];
                float v1 = acc[mt][nt][h2 * 2 + 1] + bias[gc + 1];
                if (residual) {
                    float2 rv = *(const float2*)&residual[(size_t)gr * ldc + gc];
                    v0 += rv.x; v1 += rv.y;
                }
                if (do_gelu) { v0 = gelu_f(v0); v1 = gelu_f(v1); }
                if (out_half) {
                    __half2 hv = __floats2half2_rn(v0, v1);
                    *(__half2*)((__half*)Cout + (size_t)gr * ldc + gc) = hv;
                } else {
                    float2 ov; ov.x = v0; ov.y = v1;
                    *(float2*)((float*)Cout + (size_t)gr * ldc + gc) = ov;
                }
            }
        }
    }
}

// ---------------- tensor-core flash attention (cp.async double buffer) ------
#define QSTR 72
#define QS_ELEMS (64 * QSTR)
#define ATTN_SMEM (QS_ELEMS * 5 * 2 + 2 * 64 * 64)

__global__ __launch_bounds__(128)
void attn_mma_kernel(const __half* __restrict__ Q, const __half* __restrict__ K,
                     const __half* __restrict__ V,
                     const unsigned char* __restrict__ mask,
                     __half* __restrict__ O, int Lq, int Lk,
                     int ldq, int ldkv, int causal) {
    extern __shared__ __half asm_sm[];
    __half* Qs = asm_sm;
    __half* Ks = asm_sm + QS_ELEMS;
    __half* Vs = asm_sm + 3 * QS_ELEMS;
    unsigned char* Ms = (unsigned char*)(asm_sm + 5 * QS_ELEMS);

    const int qt = blockIdx.x, h = blockIdx.y, b = blockIdx.z;
    const int tid = threadIdx.x, w = tid >> 5, lane = tid & 31;
    const int q0 = qt * 64;
    const int lr = lane >> 2;
    const int qq = (lane & 3) << 1;

    const __half* Qb = Q + ((size_t)(b * Lq + q0)) * ldq + h * DK_;
    const __half* Kb = K + ((size_t)b * Lk) * ldkv + h * DK_;
    const __half* Vb = V + ((size_t)b * Lk) * ldkv + h * DK_;

    const __half2 qscale = __float2half2_rn(0.125f);
    #pragma unroll
    for (int p = 0; p < 4; p++) {
        int idx = p * 128 + tid;
        int r = idx >> 3, c8 = (idx & 7) << 3;
        uint4 d = *(const uint4*)&Qb[(size_t)r * ldq + c8];
        __half2* hp = (__half2*)&d;
        #pragma unroll
        for (int j = 0; j < 4; j++) hp[j] = __hmul2(hp[j], qscale);
        *(uint4*)&Qs[r * QSTR + c8] = d;
    }

    #define LOAD_KV(kt, buf) do {                                                  \
        int kg_ = (kt) * 64;                                                       \
        __half* kb_ = Ks + (buf) * QS_ELEMS;                                       \
        __half* vb_ = Vs + (buf) * QS_ELEMS;                                       \
        _Pragma("unroll")                                                          \
        for (int p = 0; p < 4; p++) {                                              \
            int idx = p * 128 + tid;                                               \
            int r = idx >> 3, c8 = (idx & 7) << 3;                                 \
            unsigned dk = smem_u32(kb_ + r * QSTR + c8);                           \
            asm volatile("cp.async.cg.shared.global [%0], [%1], 16;" ::            \
                "r"(dk), "l"(&Kb[(size_t)(kg_ + r) * ldkv + c8]));                 \
            unsigned dv = smem_u32(vb_ + r * QSTR + c8);                           \
            asm volatile("cp.async.cg.shared.global [%0], [%1], 16;" ::            \
                "r"(dv), "l"(&Vb[(size_t)(kg_ + r) * ldkv + c8]));                 \
        }                                                                          \
        if (mask) {                                                                \
            unsigned char* mb_ = Ms + (buf) * 4096;                                \
            _Pragma("unroll")                                                      \
            for (int p = 0; p < 2; p++) {                                          \
                int idx = p * 128 + tid;                                           \
                int r = idx >> 2, c16 = (idx & 3) << 4;                            \
                unsigned dm = smem_u32(mb_ + r * 64 + c16);                        \
                asm volatile("cp.async.cg.shared.global [%0], [%1], 16;" ::        \
                    "r"(dm), "l"(mask + ((size_t)(b * Lq + q0 + r)) * Lk + kg_ + c16)); \
            }                                                                      \
        }                                                                          \
        asm volatile("cp.async.commit_group;");                                    \
    } while (0)

    LOAD_KV(0, 0);
    __syncthreads();

    unsigned qf[4][4];
    #pragma unroll
    for (int kc = 0; kc < 4; kc++) {
        int r = w * 16 + (lane & 15);
        int c = kc * 16 + ((lane >> 4) << 3);
        unsigned addr = smem_u32(Qs + r * QSTR + c);
        asm volatile("ldmatrix.sync.aligned.m8n8.x4.shared.b16 {%0,%1,%2,%3}, [%4];"
            : "=r"(qf[kc][0]), "=r"(qf[kc][1]), "=r"(qf[kc][2]), "=r"(qf[kc][3])
            : "r"(addr));
    }

    float o[8][4];
    #pragma unroll
    for (int i = 0; i < 8; i++)
        #pragma unroll
        for (int j = 0; j < 4; j++) o[i][j] = 0.f;
    float mrow[2] = {-1e30f, -1e30f}, lrow[2] = {0.f, 0.f};

    const int ntile = causal ? (qt + 1) : (Lk / 64);

    for (int kt = 0; kt < ntile; kt++) {
        const int buf = kt & 1;
        asm volatile("cp.async.wait_group 0;");
        __syncthreads();
        if (kt + 1 < ntile) LOAD_KV(kt + 1, buf ^ 1);

        __half* kb = Ks + buf * QS_ELEMS;
        __half* vb = Vs + buf * QS_ELEMS;
        unsigned char* mb2 = Ms + buf * 4096;

        float s[8][4];
        #pragma unroll
        for (int i = 0; i < 8; i++)
            #pragma unroll
            for (int j = 0; j < 4; j++) s[i][j] = 0.f;

        #pragma unroll
        for (int kc = 0; kc < 4; kc++) {
            #pragma unroll
            for (int np = 0; np < 4; np++) {
                unsigned kf[4];
                int r = np * 16 + (lane & 15);
                int c = kc * 16 + ((lane >> 4) << 3);
                unsigned addr = smem_u32(kb + r * QSTR + c);
                asm volatile("ldmatrix.sync.aligned.m8n8.x4.shared.b16 {%0,%1,%2,%3}, [%4];"
                    : "=r"(kf[0]), "=r"(kf[1]), "=r"(kf[2]), "=r"(kf[3])
                    : "r"(addr));
                mma_16816(s[2 * np],     qf[kc], kf[0], kf[2]);
                mma_16816(s[2 * np + 1], qf[kc], kf[1], kf[3]);
            }
        }

        if (mask) {
            int r0 = w * 16 + lr, r1 = r0 + 8;
            #pragma unroll
            for (int nt = 0; nt < 8; nt++) {
                int cc = nt * 8 + qq;
                if (mb2[r0 * 64 + cc])     s[nt][0] = -3.0e38f;
                if (mb2[r0 * 64 + cc + 1]) s[nt][1] = -3.0e38f;
                if (mb2[r1 * 64 + cc])     s[nt][2] = -3.0e38f;
                if (mb2[r1 * 64 + cc + 1]) s[nt][3] = -3.0e38f;
            }
        }
        if (causal && kt == qt) {
            int r0 = w * 16 + lr, r1 = r0 + 8;
            #pragma unroll
            for (int nt = 0; nt < 8; nt++) {
                int cc = nt * 8 + qq;
                if (cc > r0)     s[nt][0] = -3.0e38f;
                if (cc + 1 > r0) s[nt][1] = -3.0e38f;
                if (cc > r1)     s[nt][2] = -3.0e38f;
                if (cc + 1 > r1) s[nt][3] = -3.0e38f;
            }
        }

        #pragma unroll
        for (int r = 0; r < 2; r++) {
            float mx = -3.0e38f;
            #pragma unroll
            for (int nt = 0; nt < 8; nt++)
                mx = fmaxf(mx, fmaxf(s[nt][2 * r], s[nt][2 * r + 1]));
            mx = fmaxf(mx, __shfl_xor_sync(0xffffffffu, mx, 1));
            mx = fmaxf(mx, __shfl_xor_sync(0xffffffffu, mx, 2));
            float mn   = fmaxf(mrow[r], mx);
            float corr = __expf(mrow[r] - mn);
            mrow[r] = mn;
            float ls = 0.f;
            #pragma unroll
            for (int nt = 0; nt < 8; nt++) {
                s[nt][2 * r]     = __expf(s[nt][2 * r]     - mn);
                s[nt][2 * r + 1] = __expf(s[nt][2 * r + 1] - mn);
                ls += s[nt][2 * r] + s[nt][2 * r + 1];
            }
            ls += __shfl_xor_sync(0xffffffffu, ls, 1);
            ls += __shfl_xor_sync(0xffffffffu, ls, 2);
            lrow[r] = lrow[r] * corr + ls;
            #pragma unroll
            for (int nt = 0; nt < 8; nt++) {
                o[nt][2 * r]     *= corr;
                o[nt][2 * r + 1] *= corr;
            }
        }

        #pragma unroll
        for (int kc = 0; kc < 4; kc++) {
            unsigned pa[4];
            __half2 t0 = __floats2half2_rn(s[2 * kc][0],     s[2 * kc][1]);
            __half2 t1 = __floats2half2_rn(s[2 * kc][2],     s[2 * kc][3]);
            __half2 t2 = __floats2half2_rn(s[2 * kc + 1][0], s[2 * kc + 1][1]);
            __half2 t3 = __floats2half2_rn(s[2 * kc + 1][2], s[2 * kc + 1][3]);
            pa[0] = *(unsigned*)&t0; pa[1] = *(unsigned*)&t1;
            pa[2] = *(unsigned*)&t2; pa[3] = *(unsigned*)&t3;
            #pragma unroll
            for (int nd = 0; nd < 4; nd++) {
                unsigned vf[4];
                int r = kc * 16 + (lane & 15);
                int c = nd * 16 + ((lane >> 4) << 3);
                unsigned addr = smem_u32(vb + r * QSTR + c);
                asm volatile("ldmatrix.sync.aligned.m8n8.x4.trans.shared.b16 {%0,%1,%2,%3}, [%4];"
                    : "=r"(vf[0]), "=r"(vf[1]), "=r"(vf[2]), "=r"(vf[3])
                    : "r"(addr));
                mma_16816(o[2 * nd],     pa, vf[0], vf[1]);
                mma_16816(o[2 * nd + 1], pa, vf[2], vf[3]);
            }
        }
    }

    #pragma unroll
    for (int r = 0; r < 2; r++) {
        float inv = 1.0f / lrow[r];
        int row = q0 + w * 16 + lr + r * 8;
        __half* op = O + (size_t)(b * Lq + row) * D_MODEL + h * DK_;
        #pragma unroll
        for (int nt = 0; nt < 8; nt++) {
            int col = nt * 8 + qq;
            __half2 hv = __floats2half2_rn(o[nt][2 * r] * inv, o[nt][2 * r + 1] * inv);
            *(__half2*)&op[col] = hv;
        }
    }
}

// ---------------- launch ---------------------------------------------------
extern "C" void kernel_launch(void* const* d_in, const int* in_sizes, int n_in,
                              void* d_out, int out_size) {
    const float* tgt      = (const float*)d_in[0];
    const float* memory   = (const float*)d_in[1];
    const unsigned char* src_pad = (const unsigned char*)d_in[2];
    // d_in[3] = tgt_mask (causal triu) — handled via causal flag
    const float* self_wq  = (const float*)d_in[4];
    const float* self_bq  = (const float*)d_in[5];
    const float* self_wk  = (const float*)d_in[6];
    const float* self_bk  = (const float*)d_in[7];
    const float* self_wv  = (const float*)d_in[8];
    const float* self_bv  = (const float*)d_in[9];
    const float* self_wo  = (const float*)d_in[10];
    const float* self_bo  = (const float*)d_in[11];
    const float* cross_wq = (const float*)d_in[12];
    const float* cross_bq = (const float*)d_in[13];
    const float* cross_wk = (const float*)d_in[14];
    const float* cross_bk = (const float*)d_in[15];
    const float* cross_wv = (const float*)d_in[16];
    const float* cross_bv = (const float*)d_in[17];
    const float* cross_wo = (const float*)d_in[18];
    const float* cross_bo = (const float*)d_in[19];
    const float* ln1_g    = (const float*)d_in[20];
    const float* ln1_b    = (const float*)d_in[21];
    const float* ln2_g    = (const float*)d_in[22];
    const float* ln2_b    = (const float*)d_in[23];
    const float* ln3_g    = (const float*)d_in[24];
    const float* ln3_b    = (const float*)d_in[25];
    const float* ffn_w1   = (const float*)d_in[26];
    const float* ffn_b1   = (const float*)d_in[27];
    const float* ffn_w2   = (const float*)d_in[28];
    const float* ffn_b2   = (const float*)d_in[29];

    float *x1, *x2, *bias3, *bias2;
    __half *qkv16, *q16, *kv16, *ln16, *ctx16, *mem16, *ffn16, *w16;
    cudaGetSymbolAddress((void**)&x1,    g_x1);
    cudaGetSymbolAddress((void**)&x2,    g_x2);
    cudaGetSymbolAddress((void**)&qkv16, g_qkv16);
    cudaGetSymbolAddress((void**)&q16,   g_q16);
    cudaGetSymbolAddress((void**)&kv16,  g_kv16);
    cudaGetSymbolAddress((void**)&ln16,  g_ln16);
    cudaGetSymbolAddress((void**)&ctx16, g_ctx16);
    cudaGetSymbolAddress((void**)&mem16, g_mem16);
    cudaGetSymbolAddress((void**)&ffn16, g_ffn16);
    cudaGetSymbolAddress((void**)&w16,   g_w16);
    cudaGetSymbolAddress((void**)&bias3, g_bias3);
    cudaGetSymbolAddress((void**)&bias2, g_bias2);

    const int MM = D_MODEL * D_MODEL;   // 1M elements
    __half* W3    = w16;                        // [1024][3072]
    __half* swo16 = w16 + 3 * MM;
    __half* cwq16 = w16 + 4 * MM;
    __half* Wkv   = w16 + 5 * MM;               // [1024][2048]
    __half* cwo16 = w16 + 7 * MM;
    __half* w1_16 = w16 + 8 * MM;               // [1024][4096]
    __half* w2_16 = w16 + 12 * MM;              // [4096][1024]

    float* out = (float*)d_out;

    cudaFuncSetAttribute(hgemm_kernel,
                         cudaFuncAttributeMaxDynamicSharedMemorySize, HG_SMEM);
    cudaFuncSetAttribute(attn_mma_kernel,
                         cudaFuncAttributeMaxDynamicSharedMemorySize, ATTN_SMEM);

    // ---- streams/events for fork-join overlap (created once, host-side) ----
    static cudaStream_t s2 = nullptr;
    static cudaEvent_t evFork = nullptr, evKV = nullptr, evW = nullptr;
    if (s2 == nullptr) {
        cudaStreamCreateWithFlags(&s2, cudaStreamNonBlocking);
        cudaEventCreateWithFlags(&evFork, cudaEventDisableTiming);
        cudaEventCreateWithFlags(&evKV,   cudaEventDisableTiming);
        cudaEventCreateWithFlags(&evW,    cudaEventDisableTiming);
    }

    dim3 gQKV(3 * D_MODEL / 128, NTOK / 128);   // (24, 32)
    dim3 gKV (2 * D_MODEL / 128, NTOK / 128);   // (16, 32)
    dim3 gD  (D_MODEL / 128,     NTOK / 128);   // (8, 32)
    dim3 gF  (DFF_ / 128,        NTOK / 128);   // (32, 32)
    dim3 gA  (LT_ / 64, NH, B_);

    // ======== fork: side stream does the cross-KV path + FFN weights ========
    cudaEventRecord(evFork, 0);
    cudaStreamWaitEvent(s2, evFork, 0);

    {   // side stream: cross K/V weights + memory convert + KV GEMM, FFN weights
        ConvArgs cb;
        cb.njobs = 3;
        cb.prefix[0] = 0;
        cb.jobs[0] = { cross_wk, Wkv,           D_MODEL, 2 * D_MODEL };
        cb.prefix[1] = MM;
        cb.jobs[1] = { cross_wv, Wkv + D_MODEL, D_MODEL, 2 * D_MODEL };
        cb.prefix[2] = 2 * MM;
        cb.jobs[2] = { memory,   mem16,         D_MODEL, D_MODEL };
        cb.prefix[3] = 2 * MM + (long long)NTOK * D_MODEL;
        long long t8 = cb.prefix[3] / 8;
        convmany_kernel<<<(unsigned)((t8 + 255) / 256), 256, 0, s2>>>(cb);
        bias_concat_kernel<<<4, 256, 0, s2>>>(self_bq, self_bk, self_bv, bias3,
                                              cross_bk, cross_bv, bias2);
        hgemm_kernel<<<gKV, 256, HG_SMEM, s2>>>(mem16, Wkv, bias2, nullptr, kv16,
                                                NTOK, 2 * D_MODEL, D_MODEL, 2 * D_MODEL, 0, 1);
        cudaEventRecord(evKV, s2);

        ConvArgs cw;
        cw.njobs = 2;
        cw.prefix[0] = 0;
        cw.jobs[0] = { ffn_w1, w1_16, DFF_,    DFF_ };
        cw.prefix[1] = (long long)D_MODEL * DFF_;
        cw.jobs[1] = { ffn_w2, w2_16, D_MODEL, D_MODEL };
        cw.prefix[2] = 2LL * D_MODEL * DFF_;
        long long w8 = cw.prefix[2] / 8;
        convmany_kernel<<<(unsigned)((w8 + 255) / 256), 256, 0, s2>>>(cw);
        cudaEventRecord(evW, s2);
    }

    // ======== main stream: self weights, then the serial chain ========
    {
        ConvArgs ca;
        ca.njobs = 6;
        ca.prefix[0] = 0;
        ca.jobs[0] = { self_wq,  W3,               D_MODEL, 3 * D_MODEL };
        ca.prefix[1] = 1 * MM;
        ca.jobs[1] = { self_wk,  W3 + D_MODEL,     D_MODEL, 3 * D_MODEL };
        ca.prefix[2] = 2 * MM;
        ca.jobs[2] = { self_wv,  W3 + 2 * D_MODEL, D_MODEL, 3 * D_MODEL };
        ca.prefix[3] = 3 * MM;
        ca.jobs[3] = { self_wo,  swo16,            D_MODEL, D_MODEL };
        ca.prefix[4] = 4 * MM;
        ca.jobs[4] = { cross_wq, cwq16,            D_MODEL, D_MODEL };
        ca.prefix[5] = 5 * MM;
        ca.jobs[5] = { cross_wo, cwo16,            D_MODEL, D_MODEL };
        ca.prefix[6] = 6 * MM;
        long long t8 = ca.prefix[6] / 8;
        convmany_kernel<<<(unsigned)((t8 + 255) / 256), 256>>>(ca);
    }

    // ---- sublayer 1: self-attention (pre-norm) ----
    ln_kernel<<<NTOK, 256>>>(tgt, ln1_g, ln1_b, ln16);
    hgemm_kernel<<<gQKV, 256, HG_SMEM>>>(ln16, W3, bias3, nullptr, qkv16,
                                         NTOK, 3 * D_MODEL, D_MODEL, 3 * D_MODEL, 0, 1);
    attn_mma_kernel<<<gA, 128, ATTN_SMEM>>>(qkv16, qkv16 + D_MODEL, qkv16 + 2 * D_MODEL,
                                            nullptr, ctx16, LT_, LT_,
                                            3 * D_MODEL, 3 * D_MODEL, 1);
    hgemm_kernel<<<gD, 256, HG_SMEM>>>(ctx16, swo16, self_bo, tgt, x1,
                                       NTOK, D_MODEL, D_MODEL, D_MODEL, 0, 0);

    // ---- sublayer 2: cross-attention (pre-norm; K/V from raw memory) ----
    ln_kernel<<<NTOK, 256>>>(x1, ln2_g, ln2_b, ln16);
    hgemm_kernel<<<gD, 256, HG_SMEM>>>(ln16, cwq16, cross_bq, nullptr, q16,
                                       NTOK, D_MODEL, D_MODEL, D_MODEL, 0, 1);
    cudaStreamWaitEvent(0, evKV, 0);   // join: kv16 ready
    attn_mma_kernel<<<gA, 128, ATTN_SMEM>>>(q16, kv16, kv16 + D_MODEL,
                                            src_pad, ctx16, LT_, LS_,
                                            D_MODEL, 2 * D_MODEL, 0);
    hgemm_kernel<<<gD, 256, HG_SMEM>>>(ctx16, cwo16, cross_bo, x1, x2,
                                       NTOK, D_MODEL, D_MODEL, D_MODEL, 0, 0);

    // ---- sublayer 3: FFN (pre-norm) ----
    ln_kernel<<<NTOK, 256>>>(x2, ln3_g, ln3_b, ln16);
    cudaStreamWaitEvent(0, evW, 0);    // join: FFN weights ready
    hgemm_kernel<<<gF, 256, HG_SMEM>>>(ln16, w1_16, ffn_b1, nullptr, ffn16,
                                       NTOK, DFF_, D_MODEL, DFF_, 1, 1);
    hgemm_kernel<<<gD, 256, HG_SMEM>>>(ffn16, w2_16, ffn_b2, x2, out,
                                       NTOK, D_MODEL, DFF_, D_MODEL, 0, 0);
}

// round 9
// speedup vs baseline: 17.6937x; 1.0335x over previous
#include <cuda_runtime.h>
#include <cuda_fp16.h>
#include <math.h>

// ---------------- problem constants ----------------
#define D_MODEL 1024
#define NH      16
#define DK_     64
#define DFF_    4096
#define B_      4
#define LT_     1024
#define LS_     1024
#define NTOK    (B_ * LT_)   // 4096 rows

// ---------------- scratch (static device globals; no allocs allowed) -------
__device__ float  g_x1 [NTOK * D_MODEL];
__device__ float  g_x2 [NTOK * D_MODEL];
__device__ __half g_qkv16[NTOK * 3 * D_MODEL];   // self q|k|v fused (ld 3072)
__device__ __half g_q16  [NTOK * D_MODEL];       // cross q
__device__ __half g_kv16 [NTOK * 2 * D_MODEL];   // cross k|v fused (ld 2048)
__device__ __half g_ln16 [NTOK * D_MODEL];
__device__ __half g_ctx16[NTOK * D_MODEL];
__device__ __half g_mem16[NTOK * D_MODEL];
__device__ __half g_ffn16[NTOK * DFF_];
// weight pool: W3(3M) | swo(1M) | cwq(1M) | Wkv(2M) | cwo(1M) | w1(4M) | w2(4M)
__device__ __half g_w16[16 * 1024 * 1024];
__device__ float  g_bias3[3 * D_MODEL];
__device__ float  g_bias2[2 * D_MODEL];

// ---------------- batched fp32 -> fp16 convert (strided dst) ---------------
struct Job { const float* src; __half* dst; int ncols; int dstride; };
struct ConvArgs { Job jobs[8]; long long prefix[9]; int njobs; };

__global__ void convmany_kernel(ConvArgs a) {
    long long g = ((long long)blockIdx.x * blockDim.x + threadIdx.x) * 8;
    if (g >= a.prefix[a.njobs]) return;
    int seg = 0;
    while (g >= a.prefix[seg + 1]) seg++;
    long long off = g - a.prefix[seg];
    Job j = a.jobs[seg];
    int row = (int)(off / j.ncols);
    int col = (int)(off - (long long)row * j.ncols);
    const float* s = j.src + off;
    __half* d = j.dst + (size_t)row * j.dstride + col;
    float4 x0 = *(const float4*)s;
    float4 x1 = *(const float4*)(s + 4);
    __half2 h0 = __floats2half2_rn(x0.x, x0.y), h1 = __floats2half2_rn(x0.z, x0.w);
    __half2 h2 = __floats2half2_rn(x1.x, x1.y), h3 = __floats2half2_rn(x1.z, x1.w);
    uint4 o;
    o.x = *(unsigned*)&h0; o.y = *(unsigned*)&h1;
    o.z = *(unsigned*)&h2; o.w = *(unsigned*)&h3;
    *(uint4*)d = o;
}

__global__ void bias_concat_kernel(const float* b0, const float* b1, const float* b2,
                                   float* d3, const float* c0, const float* c1, float* d2) {
    int t = blockIdx.x * blockDim.x + threadIdx.x;
    if (t < D_MODEL) {
        d3[t] = b0[t]; d3[D_MODEL + t] = b1[t]; d3[2 * D_MODEL + t] = b2[t];
        d2[t] = c0[t]; d2[D_MODEL + t] = c1[t];
    }
}

// ---------------- LayerNorm: fp32 in, fp16 out -----------------------------
__global__ void ln_kernel(const float* __restrict__ x, const float* __restrict__ g,
                          const float* __restrict__ b, __half* __restrict__ y) {
    int row = blockIdx.x;
    const float* xr = x + (size_t)row * D_MODEL;
    __half*      yr = y + (size_t)row * D_MODEL;
    int t = threadIdx.x;

    float4 v = *(const float4*)&xr[t * 4];
    float s  = v.x + v.y + v.z + v.w;
    float ss = v.x * v.x + v.y * v.y + v.z * v.z + v.w * v.w;

    #pragma unroll
    for (int o = 16; o; o >>= 1) {
        s  += __shfl_xor_sync(0xffffffffu, s,  o);
        ss += __shfl_xor_sync(0xffffffffu, ss, o);
    }
    __shared__ float rs[8], rss[8];
    int w = t >> 5, lane = t & 31;
    if (lane == 0) { rs[w] = s; rss[w] = ss; }
    __syncthreads();
    float tot = 0.f, tot2 = 0.f;
    #pragma unroll
    for (int i = 0; i < 8; i++) { tot += rs[i]; tot2 += rss[i]; }

    float mu  = tot * (1.0f / D_MODEL);
    float var = tot2 * (1.0f / D_MODEL) - mu * mu;
    float r   = rsqrtf(var + 1e-5f);

    float4 gv = *(const float4*)&g[t * 4];
    float4 bv = *(const float4*)&b[t * 4];
    __half2 h0 = __floats2half2_rn((v.x - mu) * r * gv.x + bv.x,
                                   (v.y - mu) * r * gv.y + bv.y);
    __half2 h1 = __floats2half2_rn((v.z - mu) * r * gv.z + bv.z,
                                   (v.w - mu) * r * gv.w + bv.w);
    uint2 o; o.x = *(unsigned*)&h0; o.y = *(unsigned*)&h1;
    *(uint2*)&yr[t * 4] = o;
}

// ---------------- GELU (tanh approximation) --------------------------------
__device__ __forceinline__ float gelu_f(float x) {
    float x3 = x * x * x;
    float t  = tanhf(0.7978845608028654f * (x + 0.044715f * x3));
    return 0.5f * x * (1.0f + t);
}

__device__ __forceinline__ unsigned smem_u32(const void* p) {
    return (unsigned)__cvta_generic_to_shared(p);
}

__device__ __forceinline__ void mma_16816(float* c, const unsigned* a,
                                          unsigned b0, unsigned b1) {
    asm volatile(
        "mma.sync.aligned.m16n8k16.row.col.f32.f16.f16.f32 "
        "{%0,%1,%2,%3}, {%4,%5,%6,%7}, {%8,%9}, {%0,%1,%2,%3};"
        : "+f"(c[0]), "+f"(c[1]), "+f"(c[2]), "+f"(c[3])
        : "r"(a[0]), "r"(a[1]), "r"(a[2]), "r"(a[3]), "r"(b0), "r"(b1));
}

// ---------------- HGEMM: BK=32, 5-stage cp.async ring, 3-tile lookahead -----
#define HBK  32
#define ASTR 40     // 32 + 8 halfs pad
#define BSTR 136    // 128 + 8 halfs pad
#define HG_STAGES 5
#define HG_SMEM (HG_STAGES * (128 * ASTR + HBK * BSTR) * 2)

__global__ __launch_bounds__(256, 2)
void hgemm_kernel(const __half* __restrict__ A, const __half* __restrict__ W,
                  const float* __restrict__ bias, const float* __restrict__ residual,
                  void* __restrict__ Cout, int M, int N, int K, int ldc,
                  int do_gelu, int out_half) {
    extern __shared__ __half hsm[];
    __half* As = hsm;                               // [5][128*ASTR]
    __half* Bs = hsm + HG_STAGES * 128 * ASTR;      // [5][HBK*BSTR]

    const int tid  = threadIdx.x;
    const int wid  = tid >> 5, lane = tid & 31;
    const int wm   = (wid & 3) << 5;
    const int wn   = (wid >> 2) << 6;
    const int row0 = blockIdx.y << 7;
    const int col0 = blockIdx.x << 7;

    const int ar0 = tid >> 2,         ac0 = (tid & 3) << 3;
    const int ar1 = (tid + 256) >> 2, ac1 = ((tid + 256) & 3) << 3;
    const int br0 = tid >> 4,         bc0 = (tid & 15) << 3;
    const int br1 = (tid + 256) >> 4, bc1 = ((tid + 256) & 15) << 3;

    float acc[2][8][4];
    #pragma unroll
    for (int i = 0; i < 2; i++)
        #pragma unroll
        for (int j = 0; j < 8; j++)
            #pragma unroll
            for (int x = 0; x < 4; x++) acc[i][j][x] = 0.f;

    const int KT = K / HBK;

    // always commits exactly one group; loads guarded by kt<KT
    #define LOAD_TILES(kt) do {                                                    \
        if ((kt) < KT) {                                                           \
            int k0 = (kt) * HBK;                                                   \
            int st = (kt) % HG_STAGES;                                             \
            __half* ab = As + st * 128 * ASTR;                                     \
            __half* bb = Bs + st * HBK * BSTR;                                     \
            unsigned d0 = smem_u32(ab + ar0 * ASTR + ac0);                         \
            asm volatile("cp.async.cg.shared.global [%0], [%1], 16;" ::            \
                "r"(d0), "l"(&A[(size_t)(row0 + ar0) * K + k0 + ac0]));            \
            unsigned d1 = smem_u32(ab + ar1 * ASTR + ac1);                         \
            asm volatile("cp.async.cg.shared.global [%0], [%1], 16;" ::            \
                "r"(d1), "l"(&A[(size_t)(row0 + ar1) * K + k0 + ac1]));            \
            unsigned d2 = smem_u32(bb + br0 * BSTR + bc0);                         \
            asm volatile("cp.async.cg.shared.global [%0], [%1], 16;" ::            \
                "r"(d2), "l"(&W[(size_t)(k0 + br0) * N + col0 + bc0]));            \
            unsigned d3 = smem_u32(bb + br1 * BSTR + bc1);                         \
            asm volatile("cp.async.cg.shared.global [%0], [%1], 16;" ::            \
                "r"(d3), "l"(&W[(size_t)(k0 + br1) * N + col0 + bc1]));            \
        }                                                                          \
        asm volatile("cp.async.commit_group;");                                    \
    } while (0)

    LOAD_TILES(0);
    LOAD_TILES(1);
    LOAD_TILES(2);

    for (int kt = 0; kt < KT; kt++) {
        const int st = kt % HG_STAGES;
        LOAD_TILES(kt + 3);                       // issue ahead of the wait
        asm volatile("cp.async.wait_group 3;");   // group kt complete
        __syncthreads();

        __half* ab = As + st * 128 * ASTR;
        __half* bb = Bs + st * HBK * BSTR;

        #pragma unroll
        for (int ks = 0; ks < 2; ks++) {
            const int kk = ks << 4;
            unsigned a[2][4];
            #pragma unroll
            for (int mt = 0; mt < 2; mt++) {
                int r = wm + (mt << 4) + (lane & 15);
                int c = kk + ((lane >> 4) << 3);
                unsigned addr = smem_u32(ab + r * ASTR + c);
                asm volatile("ldmatrix.sync.aligned.m8n8.x4.shared.b16 {%0,%1,%2,%3}, [%4];"
                    : "=r"(a[mt][0]), "=r"(a[mt][1]), "=r"(a[mt][2]), "=r"(a[mt][3])
                    : "r"(addr));
            }
            unsigned bf[4][4];
            #pragma unroll
            for (int nq = 0; nq < 4; nq++) {
                int r = kk + (lane & 15);
                int c = wn + (nq << 4) + ((lane >> 4) << 3);
                unsigned addr = smem_u32(bb + r * BSTR + c);
                asm volatile("ldmatrix.sync.aligned.m8n8.x4.trans.shared.b16 {%0,%1,%2,%3}, [%4];"
                    : "=r"(bf[nq][0]), "=r"(bf[nq][1]), "=r"(bf[nq][2]), "=r"(bf[nq][3])
                    : "r"(addr));
            }
            #pragma unroll
            for (int mt = 0; mt < 2; mt++)
                #pragma unroll
                for (int nt = 0; nt < 8; nt++)
                    mma_16816(acc[mt][nt], a[mt],
                              bf[nt >> 1][(nt & 1) * 2], bf[nt >> 1][(nt & 1) * 2 + 1]);
        }
        __syncthreads();   // all warps done with stage st before it is refilled
    }

    const int lr = lane >> 2;
    const int lc = (lane & 3) << 1;
    #pragma unroll
    for (int mt = 0; mt < 2; mt++) {
        #pragma unroll
        for (int h2 = 0; h2 < 2; h2++) {
            int gr = row0 + wm + (mt << 4) + lr + (h2 << 3);
            #pragma unroll
            for (int nt = 0; nt < 8; nt++) {
                int gc = col0 + wn + (nt << 3) + lc;
                float v0 = acc[mt][nt][h2 * 2 + 0] + bias[gc];
                float v1 = acc[mt][nt][h2 * 2 + 1] + bias[gc + 1];
                if (residual) {
                    float2 rv = *(const float2*)&residual[(size_t)gr * ldc + gc];
                    v0 += rv.x; v1 += rv.y;
                }
                if (do_gelu) { v0 = gelu_f(v0); v1 = gelu_f(v1); }
                if (out_half) {
                    __half2 hv = __floats2half2_rn(v0, v1);
                    *(__half2*)((__half*)Cout + (size_t)gr * ldc + gc) = hv;
                } else {
                    float2 ov; ov.x = v0; ov.y = v1;
                    *(float2*)((float*)Cout + (size_t)gr * ldc + gc) = ov;
                }
            }
        }
    }
}

// ---------------- tensor-core flash attention (cp.async double buffer) ------
#define QSTR 72
#define QS_ELEMS (64 * QSTR)
#define ATTN_SMEM (QS_ELEMS * 5 * 2 + 2 * 64 * 64)

__global__ __launch_bounds__(128)
void attn_mma_kernel(const __half* __restrict__ Q, const __half* __restrict__ K,
                     const __half* __restrict__ V,
                     const unsigned char* __restrict__ mask,
                     __half* __restrict__ O, int Lq, int Lk,
                     int ldq, int ldkv, int causal) {
    extern __shared__ __half asm_sm[];
    __half* Qs = asm_sm;
    __half* Ks = asm_sm + QS_ELEMS;
    __half* Vs = asm_sm + 3 * QS_ELEMS;
    unsigned char* Ms = (unsigned char*)(asm_sm + 5 * QS_ELEMS);

    // heavy causal tiles first: reverse qt so long-running CTAs start early
    const int qt = causal ? (gridDim.x - 1 - blockIdx.x) : blockIdx.x;
    const int h = blockIdx.y, b = blockIdx.z;
    const int tid = threadIdx.x, w = tid >> 5, lane = tid & 31;
    const int q0 = qt * 64;
    const int lr = lane >> 2;
    const int qq = (lane & 3) << 1;

    const __half* Qb = Q + ((size_t)(b * Lq + q0)) * ldq + h * DK_;
    const __half* Kb = K + ((size_t)b * Lk) * ldkv + h * DK_;
    const __half* Vb = V + ((size_t)b * Lk) * ldkv + h * DK_;

    const __half2 qscale = __float2half2_rn(0.125f);
    #pragma unroll
    for (int p = 0; p < 4; p++) {
        int idx = p * 128 + tid;
        int r = idx >> 3, c8 = (idx & 7) << 3;
        uint4 d = *(const uint4*)&Qb[(size_t)r * ldq + c8];
        __half2* hp = (__half2*)&d;
        #pragma unroll
        for (int j = 0; j < 4; j++) hp[j] = __hmul2(hp[j], qscale);
        *(uint4*)&Qs[r * QSTR + c8] = d;
    }

    #define LOAD_KV(kt, buf) do {                                                  \
        int kg_ = (kt) * 64;                                                       \
        __half* kb_ = Ks + (buf) * QS_ELEMS;                                       \
        __half* vb_ = Vs + (buf) * QS_ELEMS;                                       \
        _Pragma("unroll")                                                          \
        for (int p = 0; p < 4; p++) {                                              \
            int idx = p * 128 + tid;                                               \
            int r = idx >> 3, c8 = (idx & 7) << 3;                                 \
            unsigned dk = smem_u32(kb_ + r * QSTR + c8);                           \
            asm volatile("cp.async.cg.shared.global [%0], [%1], 16;" ::            \
                "r"(dk), "l"(&Kb[(size_t)(kg_ + r) * ldkv + c8]));                 \
            unsigned dv = smem_u32(vb_ + r * QSTR + c8);                           \
            asm volatile("cp.async.cg.shared.global [%0], [%1], 16;" ::            \
                "r"(dv), "l"(&Vb[(size_t)(kg_ + r) * ldkv + c8]));                 \
        }                                                                          \
        if (mask) {                                                                \
            unsigned char* mb_ = Ms + (buf) * 4096;                                \
            _Pragma("unroll")                                                      \
            for (int p = 0; p < 2; p++) {                                          \
                int idx = p * 128 + tid;                                           \
                int r = idx >> 2, c16 = (idx & 3) << 4;                            \
                unsigned dm = smem_u32(mb_ + r * 64 + c16);                        \
                asm volatile("cp.async.cg.shared.global [%0], [%1], 16;" ::        \
                    "r"(dm), "l"(mask + ((size_t)(b * Lq + q0 + r)) * Lk + kg_ + c16)); \
            }                                                                      \
        }                                                                          \
        asm volatile("cp.async.commit_group;");                                    \
    } while (0)

    LOAD_KV(0, 0);
    __syncthreads();

    unsigned qf[4][4];
    #pragma unroll
    for (int kc = 0; kc < 4; kc++) {
        int r = w * 16 + (lane & 15);
        int c = kc * 16 + ((lane >> 4) << 3);
        unsigned addr = smem_u32(Qs + r * QSTR + c);
        asm volatile("ldmatrix.sync.aligned.m8n8.x4.shared.b16 {%0,%1,%2,%3}, [%4];"
            : "=r"(qf[kc][0]), "=r"(qf[kc][1]), "=r"(qf[kc][2]), "=r"(qf[kc][3])
            : "r"(addr));
    }

    float o[8][4];
    #pragma unroll
    for (int i = 0; i < 8; i++)
        #pragma unroll
        for (int j = 0; j < 4; j++) o[i][j] = 0.f;
    float mrow[2] = {-1e30f, -1e30f}, lrow[2] = {0.f, 0.f};

    const int ntile = causal ? (qt + 1) : (Lk / 64);

    for (int kt = 0; kt < ntile; kt++) {
        const int buf = kt & 1;
        asm volatile("cp.async.wait_group 0;");
        __syncthreads();
        if (kt + 1 < ntile) LOAD_KV(kt + 1, buf ^ 1);

        __half* kb = Ks + buf * QS_ELEMS;
        __half* vb = Vs + buf * QS_ELEMS;
        unsigned char* mb2 = Ms + buf * 4096;

        float s[8][4];
        #pragma unroll
        for (int i = 0; i < 8; i++)
            #pragma unroll
            for (int j = 0; j < 4; j++) s[i][j] = 0.f;

        #pragma unroll
        for (int kc = 0; kc < 4; kc++) {
            #pragma unroll
            for (int np = 0; np < 4; np++) {
                unsigned kf[4];
                int r = np * 16 + (lane & 15);
                int c = kc * 16 + ((lane >> 4) << 3);
                unsigned addr = smem_u32(kb + r * QSTR + c);
                asm volatile("ldmatrix.sync.aligned.m8n8.x4.shared.b16 {%0,%1,%2,%3}, [%4];"
                    : "=r"(kf[0]), "=r"(kf[1]), "=r"(kf[2]), "=r"(kf[3])
                    : "r"(addr));
                mma_16816(s[2 * np],     qf[kc], kf[0], kf[2]);
                mma_16816(s[2 * np + 1], qf[kc], kf[1], kf[3]);
            }
        }

        if (mask) {
            int r0 = w * 16 + lr, r1 = r0 + 8;
            #pragma unroll
            for (int nt = 0; nt < 8; nt++) {
                int cc = nt * 8 + qq;
                if (mb2[r0 * 64 + cc])     s[nt][0] = -3.0e38f;
                if (mb2[r0 * 64 + cc + 1]) s[nt][1] = -3.0e38f;
                if (mb2[r1 * 64 + cc])     s[nt][2] = -3.0e38f;
                if (mb2[r1 * 64 + cc + 1]) s[nt][3] = -3.0e38f;
            }
        }
        if (causal && kt == qt) {
            int r0 = w * 16 + lr, r1 = r0 + 8;
            #pragma unroll
            for (int nt = 0; nt < 8; nt++) {
                int cc = nt * 8 + qq;
                if (cc > r0)     s[nt][0] = -3.0e38f;
                if (cc + 1 > r0) s[nt][1] = -3.0e38f;
                if (cc > r1)     s[nt][2] = -3.0e38f;
                if (cc + 1 > r1) s[nt][3] = -3.0e38f;
            }
        }

        #pragma unroll
        for (int r = 0; r < 2; r++) {
            float mx = -3.0e38f;
            #pragma unroll
            for (int nt = 0; nt < 8; nt++)
                mx = fmaxf(mx, fmaxf(s[nt][2 * r], s[nt][2 * r + 1]));
            mx = fmaxf(mx, __shfl_xor_sync(0xffffffffu, mx, 1));
            mx = fmaxf(mx, __shfl_xor_sync(0xffffffffu, mx, 2));
            float mn   = fmaxf(mrow[r], mx);
            float corr = __expf(mrow[r] - mn);
            mrow[r] = mn;
            float ls = 0.f;
            #pragma unroll
            for (int nt = 0; nt < 8; nt++) {
                s[nt][2 * r]     = __expf(s[nt][2 * r]     - mn);
                s[nt][2 * r + 1] = __expf(s[nt][2 * r + 1] - mn);
                ls += s[nt][2 * r] + s[nt][2 * r + 1];
            }
            ls += __shfl_xor_sync(0xffffffffu, ls, 1);
            ls += __shfl_xor_sync(0xffffffffu, ls, 2);
            lrow[r] = lrow[r] * corr + ls;
            #pragma unroll
            for (int nt = 0; nt < 8; nt++) {
                o[nt][2 * r]     *= corr;
                o[nt][2 * r + 1] *= corr;
            }
        }

        #pragma unroll
        for (int kc = 0; kc < 4; kc++) {
            unsigned pa[4];
            __half2 t0 = __floats2half2_rn(s[2 * kc][0],     s[2 * kc][1]);
            __half2 t1 = __floats2half2_rn(s[2 * kc][2],     s[2 * kc][3]);
            __half2 t2 = __floats2half2_rn(s[2 * kc + 1][0], s[2 * kc + 1][1]);
            __half2 t3 = __floats2half2_rn(s[2 * kc + 1][2], s[2 * kc + 1][3]);
            pa[0] = *(unsigned*)&t0; pa[1] = *(unsigned*)&t1;
            pa[2] = *(unsigned*)&t2; pa[3] = *(unsigned*)&t3;
            #pragma unroll
            for (int nd = 0; nd < 4; nd++) {
                unsigned vf[4];
                int r = kc * 16 + (lane & 15);
                int c = nd * 16 + ((lane >> 4) << 3);
                unsigned addr = smem_u32(vb + r * QSTR + c);
                asm volatile("ldmatrix.sync.aligned.m8n8.x4.trans.shared.b16 {%0,%1,%2,%3}, [%4];"
                    : "=r"(vf[0]), "=r"(vf[1]), "=r"(vf[2]), "=r"(vf[3])
                    : "r"(addr));
                mma_16816(o[2 * nd],     pa, vf[0], vf[1]);
                mma_16816(o[2 * nd + 1], pa, vf[2], vf[3]);
            }
        }
    }

    #pragma unroll
    for (int r = 0; r < 2; r++) {
        float inv = 1.0f / lrow[r];
        int row = q0 + w * 16 + lr + r * 8;
        __half* op = O + (size_t)(b * Lq + row) * D_MODEL + h * DK_;
        #pragma unroll
        for (int nt = 0; nt < 8; nt++) {
            int col = nt * 8 + qq;
            __half2 hv = __floats2half2_rn(o[nt][2 * r] * inv, o[nt][2 * r + 1] * inv);
            *(__half2*)&op[col] = hv;
        }
    }
}

// ---------------- launch ---------------------------------------------------
extern "C" void kernel_launch(void* const* d_in, const int* in_sizes, int n_in,
                              void* d_out, int out_size) {
    const float* tgt      = (const float*)d_in[0];
    const float* memory   = (const float*)d_in[1];
    const unsigned char* src_pad = (const unsigned char*)d_in[2];
    // d_in[3] = tgt_mask (causal triu) — handled via causal flag
    const float* self_wq  = (const float*)d_in[4];
    const float* self_bq  = (const float*)d_in[5];
    const float* self_wk  = (const float*)d_in[6];
    const float* self_bk  = (const float*)d_in[7];
    const float* self_wv  = (const float*)d_in[8];
    const float* self_bv  = (const float*)d_in[9];
    const float* self_wo  = (const float*)d_in[10];
    const float* self_bo  = (const float*)d_in[11];
    const float* cross_wq = (const float*)d_in[12];
    const float* cross_bq = (const float*)d_in[13];
    const float* cross_wk = (const float*)d_in[14];
    const float* cross_bk = (const float*)d_in[15];
    const float* cross_wv = (const float*)d_in[16];
    const float* cross_bv = (const float*)d_in[17];
    const float* cross_wo = (const float*)d_in[18];
    const float* cross_bo = (const float*)d_in[19];
    const float* ln1_g    = (const float*)d_in[20];
    const float* ln1_b    = (const float*)d_in[21];
    const float* ln2_g    = (const float*)d_in[22];
    const float* ln2_b    = (const float*)d_in[23];
    const float* ln3_g    = (const float*)d_in[24];
    const float* ln3_b    = (const float*)d_in[25];
    const float* ffn_w1   = (const float*)d_in[26];
    const float* ffn_b1   = (const float*)d_in[27];
    const float* ffn_w2   = (const float*)d_in[28];
    const float* ffn_b2   = (const float*)d_in[29];

    float *x1, *x2, *bias3, *bias2;
    __half *qkv16, *q16, *kv16, *ln16, *ctx16, *mem16, *ffn16, *w16;
    cudaGetSymbolAddress((void**)&x1,    g_x1);
    cudaGetSymbolAddress((void**)&x2,    g_x2);
    cudaGetSymbolAddress((void**)&qkv16, g_qkv16);
    cudaGetSymbolAddress((void**)&q16,   g_q16);
    cudaGetSymbolAddress((void**)&kv16,  g_kv16);
    cudaGetSymbolAddress((void**)&ln16,  g_ln16);
    cudaGetSymbolAddress((void**)&ctx16, g_ctx16);
    cudaGetSymbolAddress((void**)&mem16, g_mem16);
    cudaGetSymbolAddress((void**)&ffn16, g_ffn16);
    cudaGetSymbolAddress((void**)&w16,   g_w16);
    cudaGetSymbolAddress((void**)&bias3, g_bias3);
    cudaGetSymbolAddress((void**)&bias2, g_bias2);

    const int MM = D_MODEL * D_MODEL;   // 1M elements
    __half* W3    = w16;                        // [1024][3072]
    __half* swo16 = w16 + 3 * MM;
    __half* cwq16 = w16 + 4 * MM;
    __half* Wkv   = w16 + 5 * MM;               // [1024][2048]
    __half* cwo16 = w16 + 7 * MM;
    __half* w1_16 = w16 + 8 * MM;               // [1024][4096]
    __half* w2_16 = w16 + 12 * MM;              // [4096][1024]

    float* out = (float*)d_out;

    cudaFuncSetAttribute(hgemm_kernel,
                         cudaFuncAttributeMaxDynamicSharedMemorySize, HG_SMEM);
    cudaFuncSetAttribute(attn_mma_kernel,
                         cudaFuncAttributeMaxDynamicSharedMemorySize, ATTN_SMEM);

    // ---- streams/events for fork-join overlap (created once, host-side) ----
    static cudaStream_t s2 = nullptr;
    static cudaEvent_t evFork = nullptr, evSelfW = nullptr, evKV = nullptr, evW = nullptr;
    if (s2 == nullptr) {
        cudaStreamCreateWithFlags(&s2, cudaStreamNonBlocking);
        cudaEventCreateWithFlags(&evFork,  cudaEventDisableTiming);
        cudaEventCreateWithFlags(&evSelfW, cudaEventDisableTiming);
        cudaEventCreateWithFlags(&evKV,    cudaEventDisableTiming);
        cudaEventCreateWithFlags(&evW,     cudaEventDisableTiming);
    }

    dim3 gQKV(3 * D_MODEL / 128, NTOK / 128);   // (24, 32)
    dim3 gKV (2 * D_MODEL / 128, NTOK / 128);   // (16, 32)
    dim3 gD  (D_MODEL / 128,     NTOK / 128);   // (8, 32)
    dim3 gF  (DFF_ / 128,        NTOK / 128);   // (32, 32)
    dim3 gA  (LT_ / 64, NH, B_);

    // ======== fork: side stream does ALL weight prep + cross-KV path ========
    cudaEventRecord(evFork, 0);
    cudaStreamWaitEvent(s2, evFork, 0);

    {   // 1) main-path weights (QKV fused + projections) + bias concat
        ConvArgs ca;
        ca.njobs = 6;
        ca.prefix[0] = 0;
        ca.jobs[0] = { self_wq,  W3,               D_MODEL, 3 * D_MODEL };
        ca.prefix[1] = 1 * MM;
        ca.jobs[1] = { self_wk,  W3 + D_MODEL,     D_MODEL, 3 * D_MODEL };
        ca.prefix[2] = 2 * MM;
        ca.jobs[2] = { self_wv,  W3 + 2 * D_MODEL, D_MODEL, 3 * D_MODEL };
        ca.prefix[3] = 3 * MM;
        ca.jobs[3] = { self_wo,  swo16,            D_MODEL, D_MODEL };
        ca.prefix[4] = 4 * MM;
        ca.jobs[4] = { cross_wq, cwq16,            D_MODEL, D_MODEL };
        ca.prefix[5] = 5 * MM;
        ca.jobs[5] = { cross_wo, cwo16,            D_MODEL, D_MODEL };
        ca.prefix[6] = 6 * MM;
        long long t8 = ca.prefix[6] / 8;
        convmany_kernel<<<(unsigned)((t8 + 255) / 256), 256, 0, s2>>>(ca);
        bias_concat_kernel<<<4, 256, 0, s2>>>(self_bq, self_bk, self_bv, bias3,
                                              cross_bk, cross_bv, bias2);
        cudaEventRecord(evSelfW, s2);

        // 2) cross K/V weights + memory convert + KV GEMM
        ConvArgs cb;
        cb.njobs = 3;
        cb.prefix[0] = 0;
        cb.jobs[0] = { cross_wk, Wkv,           D_MODEL, 2 * D_MODEL };
        cb.prefix[1] = MM;
        cb.jobs[1] = { cross_wv, Wkv + D_MODEL, D_MODEL, 2 * D_MODEL };
        cb.prefix[2] = 2 * MM;
        cb.jobs[2] = { memory,   mem16,         D_MODEL, D_MODEL };
        cb.prefix[3] = 2 * MM + (long long)NTOK * D_MODEL;
        long long u8 = cb.prefix[3] / 8;
        convmany_kernel<<<(unsigned)((u8 + 255) / 256), 256, 0, s2>>>(cb);
        hgemm_kernel<<<gKV, 256, HG_SMEM, s2>>>(mem16, Wkv, bias2, nullptr, kv16,
                                                NTOK, 2 * D_MODEL, D_MODEL, 2 * D_MODEL, 0, 1);
        cudaEventRecord(evKV, s2);

        // 3) FFN weights
        ConvArgs cw;
        cw.njobs = 2;
        cw.prefix[0] = 0;
        cw.jobs[0] = { ffn_w1, w1_16, DFF_,    DFF_ };
        cw.prefix[1] = (long long)D_MODEL * DFF_;
        cw.jobs[1] = { ffn_w2, w2_16, D_MODEL, D_MODEL };
        cw.prefix[2] = 2LL * D_MODEL * DFF_;
        long long w8 = cw.prefix[2] / 8;
        convmany_kernel<<<(unsigned)((w8 + 255) / 256), 256, 0, s2>>>(cw);
        cudaEventRecord(evW, s2);
    }

    // ======== main stream: serial chain (starts immediately with ln1) ========
    ln_kernel<<<NTOK, 256>>>(tgt, ln1_g, ln1_b, ln16);
    cudaStreamWaitEvent(0, evSelfW, 0);   // join: main-path weights ready
    hgemm_kernel<<<gQKV, 256, HG_SMEM>>>(ln16, W3, bias3, nullptr, qkv16,
                                         NTOK, 3 * D_MODEL, D_MODEL, 3 * D_MODEL, 0, 1);
    attn_mma_kernel<<<gA, 128, ATTN_SMEM>>>(qkv16, qkv16 + D_MODEL, qkv16 + 2 * D_MODEL,
                                            nullptr, ctx16, LT_, LT_,
                                            3 * D_MODEL, 3 * D_MODEL, 1);
    hgemm_kernel<<<gD, 256, HG_SMEM>>>(ctx16, swo16, self_bo, tgt, x1,
                                       NTOK, D_MODEL, D_MODEL, D_MODEL, 0, 0);

    // ---- sublayer 2: cross-attention ----
    ln_kernel<<<NTOK, 256>>>(x1, ln2_g, ln2_b, ln16);
    hgemm_kernel<<<gD, 256, HG_SMEM>>>(ln16, cwq16, cross_bq, nullptr, q16,
                                       NTOK, D_MODEL, D_MODEL, D_MODEL, 0, 1);
    cudaStreamWaitEvent(0, evKV, 0);   // join: kv16 ready
    attn_mma_kernel<<<gA, 128, ATTN_SMEM>>>(q16, kv16, kv16 + D_MODEL,
                                            src_pad, ctx16, LT_, LS_,
                                            D_MODEL, 2 * D_MODEL, 0);
    hgemm_kernel<<<gD, 256, HG_SMEM>>>(ctx16, cwo16, cross_bo, x1, x2,
                                       NTOK, D_MODEL, D_MODEL, D_MODEL, 0, 0);

    // ---- sublayer 3: FFN ----
    ln_kernel<<<NTOK, 256>>>(x2, ln3_g, ln3_b, ln16);
    cudaStreamWaitEvent(0, evW, 0);    // join: FFN weights ready
    hgemm_kernel<<<gF, 256, HG_SMEM>>>(ln16, w1_16, ffn_b1, nullptr, ffn16,
                                       NTOK, DFF_, D_MODEL, DFF_, 1, 1);
    hgemm_kernel<<<gD, 256, HG_SMEM>>>(ffn16, w2_16, ffn_b2, x2, out,
                                       NTOK, D_MODEL, DFF_, D_MODEL, 0, 0);
}